// round 1
// baseline (speedup 1.0000x reference)
#include <cuda_runtime.h>
#include <math.h>

#define BB 2
#define SS 2048
#define DD 1024
#define NH 16
#define HD 64
#define ROWS (BB*SS)          // 4096

// ---------------- scratch (static device globals: no allocation) ------------
__device__ float g_xn[ROWS*DD];          // 16 MB
__device__ float g_qkv[ROWS*3*DD];       // 48 MB
__device__ float g_ctx[ROWS*DD];         // 16 MB
__device__ float g_btab[SS];             // 8 KB: beta*log1p(dist)

// ---------------- LayerNorm: one block per row ------------------------------
__global__ void ln_kernel(const float* __restrict__ x,
                          const float* __restrict__ gamma,
                          const float* __restrict__ lnb,
                          float* __restrict__ out) {
    int row = blockIdx.x;
    const float* xr = x + (size_t)row * DD;
    float v[4];
    float s = 0.f;
#pragma unroll
    for (int i = 0; i < 4; i++) { v[i] = xr[threadIdx.x + 256*i]; s += v[i]; }
    __shared__ float red[8];
#pragma unroll
    for (int o = 16; o > 0; o >>= 1) s += __shfl_xor_sync(0xffffffffu, s, o);
    if ((threadIdx.x & 31) == 0) red[threadIdx.x >> 5] = s;
    __syncthreads();
    float tot = 0.f;
#pragma unroll
    for (int i = 0; i < 8; i++) tot += red[i];
    float mean = tot * (1.f/DD);
    float vs = 0.f;
#pragma unroll
    for (int i = 0; i < 4; i++) { float d = v[i]-mean; vs += d*d; }
    __syncthreads();
#pragma unroll
    for (int o = 16; o > 0; o >>= 1) vs += __shfl_xor_sync(0xffffffffu, vs, o);
    if ((threadIdx.x & 31) == 0) red[threadIdx.x >> 5] = vs;
    __syncthreads();
    float vtot = 0.f;
#pragma unroll
    for (int i = 0; i < 8; i++) vtot += red[i];
    float rstd = rsqrtf(vtot*(1.f/DD) + 1e-5f);
    float* orow = out + (size_t)row * DD;
#pragma unroll
    for (int i = 0; i < 4; i++) {
        int c = threadIdx.x + 256*i;
        orow[c] = (v[i]-mean)*rstd*gamma[c] + lnb[c];
    }
}

// ---------------- bias table: beta * log1p(dist) ----------------------------
__global__ void bias_kernel(const float* __restrict__ beta, float* __restrict__ tab) {
    int i = blockIdx.x*256 + threadIdx.x;
    if (i < SS) tab[i] = beta[0] * log1pf((float)i);
}

// ---------------- classic 128x128x8 SGEMM, fused bias (+residual) ----------
template<bool RESID>
__global__ void __launch_bounds__(256, 2)
sgemm_bias(const float* __restrict__ A, const float* __restrict__ Bm,
           const float* __restrict__ bias, const float* __restrict__ resid,
           float* __restrict__ C, int M, int N, int K) {
    __shared__ float As[8][128];
    __shared__ float Bs[8][132];
    int bm = blockIdx.y * 128, bn = blockIdx.x * 128;
    int tid = threadIdx.x;
    int tx = tid & 15, ty = tid >> 4;
    int a_r = tid >> 1, a_c = (tid & 1) * 4;
    int b_r = tid >> 5, b_c = (tid & 31) * 4;
    const float* Aptr = A + (size_t)(bm + a_r) * K + a_c;
    const float* Bptr = Bm + (size_t)b_r * N + bn + b_c;
    float acc[8][8] = {};
    for (int k0 = 0; k0 < K; k0 += 8) {
        float4 av = *(const float4*)(Aptr + k0);
        As[a_c+0][a_r] = av.x; As[a_c+1][a_r] = av.y;
        As[a_c+2][a_r] = av.z; As[a_c+3][a_r] = av.w;
        float4 bv = *(const float4*)(Bptr + (size_t)k0 * N);
        *(float4*)&Bs[b_r][b_c] = bv;
        __syncthreads();
#pragma unroll
        for (int kk = 0; kk < 8; kk++) {
            float a[8], b[8];
#pragma unroll
            for (int i = 0; i < 8; i++) a[i] = As[kk][ty*8+i];
#pragma unroll
            for (int j = 0; j < 8; j++) b[j] = Bs[kk][tx*8+j];
#pragma unroll
            for (int i = 0; i < 8; i++)
#pragma unroll
                for (int j = 0; j < 8; j++)
                    acc[i][j] = fmaf(a[i], b[j], acc[i][j]);
        }
        __syncthreads();
    }
#pragma unroll
    for (int i = 0; i < 8; i++) {
        int row = bm + ty*8 + i;
#pragma unroll
        for (int j = 0; j < 8; j++) {
            int col = bn + tx*8 + j;
            float v = acc[i][j] + bias[col];
            if (RESID) v += resid[(size_t)row * N + col];
            C[(size_t)row * N + col] = v;
        }
    }
}

// ---------------- flash attention (fp32) with temporal-bias table -----------
// grid: (S/BQ, NH, BB), 256 threads. BQ=128, BK=64.
// smem: Qs[64][132] (dd-major), Ks[64][68] (dd-major), Vs[64][64], Ps[64][132]
#define BQ 128
#define BK 64
#define FLASH_SMEM ((64*132 + 64*68 + 64*64 + 64*132) * 4)

__global__ void __launch_bounds__(256, 1)
flash_kernel(const float* __restrict__ qkv, const float* __restrict__ btab,
             float* __restrict__ ctx) {
    extern __shared__ float sm[];
    float* Qs = sm;               // [dd][q]  64 x 132
    float* Ks = Qs + 64*132;      // [dd][kk] 64 x 68
    float* Vs = Ks + 64*68;       // [kk][dd] 64 x 64
    float* Ps = Vs + 64*64;       // [kk][q]  64 x 132

    int tid = threadIdx.x;
    int q0 = blockIdx.x * BQ;
    int h = blockIdx.y, b = blockIdx.z;
    const float* base = qkv + (size_t)b * SS * (3*DD);
    int tx = tid & 15, ty = tid >> 4;

    // load Q tile transposed: Qs[dd][q]
#pragma unroll
    for (int r = 0; r < 8; r++) {
        int i = tid + 256*r;              // 0..2047
        int row = i >> 4, d4 = (i & 15) * 4;
        float4 qv = *(const float4*)(base + (size_t)(q0+row)*(3*DD) + h*HD + d4);
        Qs[(d4+0)*132+row] = qv.x; Qs[(d4+1)*132+row] = qv.y;
        Qs[(d4+2)*132+row] = qv.z; Qs[(d4+3)*132+row] = qv.w;
    }

    float o[8][4] = {};
    float m_i[8], l_i[8];
#pragma unroll
    for (int i = 0; i < 8; i++) { m_i[i] = -INFINITY; l_i[i] = 0.f; }

    for (int kt = 0; kt < SS/BK; kt++) {
        __syncthreads();   // prior O-GEMM reads of Ks/Vs done; Q visible on iter 0
        // load K (transposed) and V tiles
#pragma unroll
        for (int r = 0; r < 4; r++) {
            int i = tid + 256*r;          // 0..1023
            int row = i >> 4, d4 = (i & 15) * 4;
            int kg = kt*BK + row;
            float4 kv = *(const float4*)(base + (size_t)kg*(3*DD) + DD + h*HD + d4);
            Ks[(d4+0)*68+row] = kv.x; Ks[(d4+1)*68+row] = kv.y;
            Ks[(d4+2)*68+row] = kv.z; Ks[(d4+3)*68+row] = kv.w;
            float4 vv = *(const float4*)(base + (size_t)kg*(3*DD) + 2*DD + h*HD + d4);
            *(float4*)&Vs[row*64 + d4] = vv;
        }
        __syncthreads();

        // S = Q @ K^T  (8x4 per thread)
        float s[8][4] = {};
#pragma unroll 4
        for (int dd = 0; dd < 64; dd++) {
            float a[8], bb[4];
#pragma unroll
            for (int i = 0; i < 8; i++) a[i] = Qs[dd*132 + ty*8 + i];
#pragma unroll
            for (int j = 0; j < 4; j++) bb[j] = Ks[dd*68 + tx*4 + j];
#pragma unroll
            for (int i = 0; i < 8; i++)
#pragma unroll
                for (int j = 0; j < 4; j++)
                    s[i][j] = fmaf(a[i], bb[j], s[i][j]);
        }

        // scale + temporal bias + online softmax
#pragma unroll
        for (int i = 0; i < 8; i++) {
            int qg = q0 + ty*8 + i;
            float mx = -INFINITY;
#pragma unroll
            for (int j = 0; j < 4; j++) {
                int kg = kt*BK + tx*4 + j;
                int dist = qg - kg; dist = dist < 0 ? -dist : dist;
                float sv = s[i][j]*0.125f + btab[dist];
                s[i][j] = sv;
                mx = fmaxf(mx, sv);
            }
#pragma unroll
            for (int o2 = 8; o2 > 0; o2 >>= 1)
                mx = fmaxf(mx, __shfl_xor_sync(0xffffffffu, mx, o2, 16));
            float newm = fmaxf(m_i[i], mx);
            float corr = __expf(m_i[i] - newm);
            float rs = 0.f;
            float p[4];
#pragma unroll
            for (int j = 0; j < 4; j++) { p[j] = __expf(s[i][j] - newm); rs += p[j]; }
#pragma unroll
            for (int o2 = 8; o2 > 0; o2 >>= 1)
                rs += __shfl_xor_sync(0xffffffffu, rs, o2, 16);
            l_i[i] = l_i[i]*corr + rs;
            m_i[i] = newm;
#pragma unroll
            for (int j = 0; j < 4; j++) o[i][j] *= corr;
#pragma unroll
            for (int j = 0; j < 4; j++) Ps[(tx*4+j)*132 + ty*8 + i] = p[j];
        }
        __syncthreads();

        // O += P @ V
#pragma unroll 4
        for (int kk = 0; kk < 64; kk++) {
            float a[8], bb[4];
#pragma unroll
            for (int i = 0; i < 8; i++) a[i] = Ps[kk*132 + ty*8 + i];
#pragma unroll
            for (int j = 0; j < 4; j++) bb[j] = Vs[kk*64 + tx*4 + j];
#pragma unroll
            for (int i = 0; i < 8; i++)
#pragma unroll
                for (int j = 0; j < 4; j++)
                    o[i][j] = fmaf(a[i], bb[j], o[i][j]);
        }
    }

    // write ctx[b, q, h*64+dd]
#pragma unroll
    for (int i = 0; i < 8; i++) {
        float inv = 1.f / l_i[i];
        int row = q0 + ty*8 + i;
#pragma unroll
        for (int j = 0; j < 4; j++)
            ctx[((size_t)b*SS + row)*DD + h*HD + tx*4 + j] = o[i][j] * inv;
    }
}

// ---------------- launcher --------------------------------------------------
extern "C" void kernel_launch(void* const* d_in, const int* in_sizes, int n_in,
                              void* d_out, int out_size) {
    const float* x      = (const float*)d_in[0];
    const float* w_qkv  = (const float*)d_in[1];
    const float* b_qkv  = (const float*)d_in[2];
    const float* w_out  = (const float*)d_in[3];
    const float* b_out  = (const float*)d_in[4];
    const float* gamma  = (const float*)d_in[5];
    const float* lnb    = (const float*)d_in[6];
    const float* beta   = (const float*)d_in[7];
    float* out = (float*)d_out;

    float *xn, *qkv, *ctx, *btab;
    cudaGetSymbolAddress((void**)&xn,   g_xn);
    cudaGetSymbolAddress((void**)&qkv,  g_qkv);
    cudaGetSymbolAddress((void**)&ctx,  g_ctx);
    cudaGetSymbolAddress((void**)&btab, g_btab);

    cudaFuncSetAttribute(flash_kernel,
                         cudaFuncAttributeMaxDynamicSharedMemorySize, FLASH_SMEM);

    ln_kernel<<<ROWS, 256>>>(x, gamma, lnb, xn);
    bias_kernel<<<(SS+255)/256, 256>>>(beta, btab);
    sgemm_bias<false><<<dim3(3*DD/128, ROWS/128), 256>>>(
        xn, w_qkv, b_qkv, nullptr, qkv, ROWS, 3*DD, DD);
    flash_kernel<<<dim3(SS/BQ, NH, BB), 256, FLASH_SMEM>>>(qkv, btab, ctx);
    sgemm_bias<true><<<dim3(DD/128, ROWS/128), 256>>>(
        ctx, w_out, b_out, x, out, ROWS, DD, DD);
}

// round 3
// speedup vs baseline: 1.3610x; 1.3610x over previous
#include <cuda_runtime.h>
#include <cuda_bf16.h>
#include <math.h>
#include <stdint.h>

#define BB 2
#define SS 2048
#define DD 1024
#define NH 16
#define HD 64
#define ROWS (BB*SS)          // 4096
#define GK DD                 // 1024

// ---------------- scratch (static device globals: no allocation) ------------
__device__ float g_xn[ROWS*DD];          // 16 MB
__device__ float g_qkv[ROWS*3*DD];       // 48 MB
__device__ float g_ctx[ROWS*DD];         // 16 MB
__device__ float g_btab[SS];             // 8 KB
__device__ float g_wtq[3*DD*DD];         // 12 MB: w_qkv transposed [N,K]
__device__ float g_wto[DD*DD];           // 4 MB : w_out transposed [N,K]

// ---------------- LayerNorm ------------------------------------------------
__global__ void ln_kernel(const float* __restrict__ x,
                          const float* __restrict__ gamma,
                          const float* __restrict__ lnb,
                          float* __restrict__ out) {
    int row = blockIdx.x;
    const float* xr = x + (size_t)row * DD;
    float v[4];
    float s = 0.f;
#pragma unroll
    for (int i = 0; i < 4; i++) { v[i] = xr[threadIdx.x + 256*i]; s += v[i]; }
    __shared__ float red[8];
#pragma unroll
    for (int o = 16; o > 0; o >>= 1) s += __shfl_xor_sync(0xffffffffu, s, o);
    if ((threadIdx.x & 31) == 0) red[threadIdx.x >> 5] = s;
    __syncthreads();
    float tot = 0.f;
#pragma unroll
    for (int i = 0; i < 8; i++) tot += red[i];
    float mean = tot * (1.f/DD);
    float vs = 0.f;
#pragma unroll
    for (int i = 0; i < 4; i++) { float d = v[i]-mean; vs += d*d; }
    __syncthreads();
#pragma unroll
    for (int o = 16; o > 0; o >>= 1) vs += __shfl_xor_sync(0xffffffffu, vs, o);
    if ((threadIdx.x & 31) == 0) red[threadIdx.x >> 5] = vs;
    __syncthreads();
    float vtot = 0.f;
#pragma unroll
    for (int i = 0; i < 8; i++) vtot += red[i];
    float rstd = rsqrtf(vtot*(1.f/DD) + 1e-5f);
    float* orow = out + (size_t)row * DD;
#pragma unroll
    for (int i = 0; i < 4; i++) {
        int c = threadIdx.x + 256*i;
        orow[c] = (v[i]-mean)*rstd*gamma[c] + lnb[c];
    }
}

__global__ void bias_kernel(const float* __restrict__ beta, float* __restrict__ tab) {
    int i = blockIdx.x*256 + threadIdx.x;
    if (i < SS) tab[i] = beta[0] * log1pf((float)i);
}

// ---------------- weight transpose: in[K][N] -> out[N][K] -------------------
__global__ void transpose_kernel(const float* __restrict__ in, float* __restrict__ out,
                                 int K, int N) {
    __shared__ float t[32][33];
    int n0 = blockIdx.x*32, k0 = blockIdx.y*32;
    int tx = threadIdx.x, ty = threadIdx.y;   // 32 x 8
#pragma unroll
    for (int i = 0; i < 32; i += 8)
        t[ty+i][tx] = in[(size_t)(k0+ty+i)*N + n0+tx];
    __syncthreads();
#pragma unroll
    for (int i = 0; i < 32; i += 8)
        out[(size_t)(n0+ty+i)*K + k0+tx] = t[tx][ty+i];
}

// =================== split-bf16 mma.sync GEMM ===============================
// C[M,N] = A[M,GK] @ Bt[N,GK]^T (+bias +resid), 3-pass bf16 split (~fp32 acc).
// CTA tile 128x128, k-chunk 32. 8 warps = 4(m) x 2(n); warp tile 32x64.
// Operands staged in SMEM pre-permuted into mma fragment layout.

__device__ __forceinline__ uint32_t bf16x2_hi(float x0, float x1,
                                              float& r0, float& r1) {
    __nv_bfloat16 h0 = __float2bfloat16_rn(x0);
    __nv_bfloat16 h1 = __float2bfloat16_rn(x1);
    r0 = x0 - __bfloat162float(h0);
    r1 = x1 - __bfloat162float(h1);
    return ((uint32_t)__bfloat16_as_ushort(h1) << 16) | __bfloat16_as_ushort(h0);
}
__device__ __forceinline__ uint32_t bf16x2_of(float x0, float x1) {
    __nv_bfloat16 h0 = __float2bfloat16_rn(x0);
    __nv_bfloat16 h1 = __float2bfloat16_rn(x1);
    return ((uint32_t)__bfloat16_as_ushort(h1) << 16) | __bfloat16_as_ushort(h0);
}

#define MMA_BF16(d, a, b) \
    asm volatile("mma.sync.aligned.m16n8k16.row.col.f32.bf16.bf16.f32 " \
        "{%0,%1,%2,%3}, {%4,%5,%6,%7}, {%8,%9}, {%0,%1,%2,%3};" \
        : "+f"((d)[0]), "+f"((d)[1]), "+f"((d)[2]), "+f"((d)[3]) \
        : "r"((a).x), "r"((a).y), "r"((a).z), "r"((a).w), \
          "r"((b).x), "r"((b).y))

template<bool RESID>
__global__ void __launch_bounds__(256)
gemm_bf16x3(const float* __restrict__ A, const float* __restrict__ Bt,
            const float* __restrict__ bias, const float* __restrict__ resid,
            float* __restrict__ C, int N) {
    // fragment-layout smem: A [s][mtile][lane] uint4, B [s][ntile][lane] uint2
    __shared__ uint4 AfH[2][8][32];
    __shared__ uint4 AfL[2][8][32];
    __shared__ uint2 BfH[2][16][32];
    __shared__ uint2 BfL[2][16][32];

    int tid = threadIdx.x, lane = tid & 31, wid = tid >> 5;
    int bm = blockIdx.y * 128, bn = blockIdx.x * 128;
    int wm = wid >> 1, wn = wid & 1;

    const float* Ag = A  + (size_t)bm * GK;
    const float* Bg = Bt + (size_t)bn * GK;

    float acc[2][8][4] = {};

    for (int c = 0; c < GK/32; c++) {
        // ---------- stage A (128x32) and B (128x32) into fragment layout ----
#pragma unroll
        for (int r = 0; r < 4; r++) {
            int i = tid + 256*r;          // 0..1023: row = i>>3, f4 = i&7
            int row = i >> 3, f4 = i & 7;
            int s  = f4 >> 2;
            int cc = (f4 & 3) * 4;        // 0,4,8,12 (k offset within k16)
            int t0 = (cc & 7) >> 1;       // pair index 0 or 2

            // ---- A ----
            {
                float4 av = *(const float4*)(Ag + (size_t)row*GK + c*32 + f4*4);
                float l0, l1, l2, l3;
                uint32_t h01 = bf16x2_hi(av.x, av.y, l0, l1);
                uint32_t h23 = bf16x2_hi(av.z, av.w, l2, l3);
                uint32_t lo01 = bf16x2_of(l0, l1);
                uint32_t lo23 = bf16x2_of(l2, l3);
                int rr = row & 15, mt = row >> 4;
                int slot = (cc < 8 ? 0 : 2) + (rr >> 3);
                int base = ((s*8 + mt)*32)*4;
                int i0 = base + ((rr & 7)*4 + t0)*4 + slot;
                int i1 = base + ((rr & 7)*4 + t0 + 1)*4 + slot;
                ((uint32_t*)AfH)[i0] = h01;
                ((uint32_t*)AfH)[i1] = h23;
                ((uint32_t*)AfL)[i0] = lo01;
                ((uint32_t*)AfL)[i1] = lo23;
            }
            // ---- B ----
            {
                float4 bv = *(const float4*)(Bg + (size_t)row*GK + c*32 + f4*4);
                float l0, l1, l2, l3;
                uint32_t h01 = bf16x2_hi(bv.x, bv.y, l0, l1);
                uint32_t h23 = bf16x2_hi(bv.z, bv.w, l2, l3);
                uint32_t lo01 = bf16x2_of(l0, l1);
                uint32_t lo23 = bf16x2_of(l2, l3);
                int nt = row >> 3;
                int slot = (cc < 8) ? 0 : 1;
                int base = ((s*16 + nt)*32)*2;
                int i0 = base + ((row & 7)*4 + t0)*2 + slot;
                int i1 = base + ((row & 7)*4 + t0 + 1)*2 + slot;
                ((uint32_t*)BfH)[i0] = h01;
                ((uint32_t*)BfH)[i1] = h23;
                ((uint32_t*)BfL)[i0] = lo01;
                ((uint32_t*)BfL)[i1] = lo23;
            }
        }
        __syncthreads();

        // ---------- compute ----------
#pragma unroll
        for (int s = 0; s < 2; s++) {
            uint4 ah[2], al[2];
#pragma unroll
            for (int mi = 0; mi < 2; mi++) {
                ah[mi] = AfH[s][wm*2 + mi][lane];
                al[mi] = AfL[s][wm*2 + mi][lane];
            }
#pragma unroll
            for (int ni = 0; ni < 8; ni++) {
                uint2 bh = BfH[s][wn*8 + ni][lane];
                uint2 bl = BfL[s][wn*8 + ni][lane];
#pragma unroll
                for (int mi = 0; mi < 2; mi++) {
                    MMA_BF16(acc[mi][ni], ah[mi], bh);
                    MMA_BF16(acc[mi][ni], ah[mi], bl);
                    MMA_BF16(acc[mi][ni], al[mi], bh);
                }
            }
        }
        __syncthreads();
    }

    // ---------- epilogue ----------
    int g = lane >> 2, tq = lane & 3;
#pragma unroll
    for (int mi = 0; mi < 2; mi++) {
#pragma unroll
        for (int half = 0; half < 2; half++) {
            int row = bm + (wm*2 + mi)*16 + g + half*8;
            float* crow = C + (size_t)row * N;
            const float* rrow = resid + (size_t)row * N;
#pragma unroll
            for (int ni = 0; ni < 8; ni++) {
                int col = bn + (wn*8 + ni)*8 + tq*2;
                float2 v;
                v.x = acc[mi][ni][half*2 + 0] + bias[col];
                v.y = acc[mi][ni][half*2 + 1] + bias[col + 1];
                if (RESID) {
                    v.x += rrow[col];
                    v.y += rrow[col + 1];
                }
                *(float2*)(crow + col) = v;
            }
        }
    }
}

// ---------------- flash attention (fp32, unchanged) -------------------------
#define BQ 128
#define BK 64
#define FLASH_SMEM ((64*132 + 64*68 + 64*64 + 64*132) * 4)

__global__ void __launch_bounds__(256, 1)
flash_kernel(const float* __restrict__ qkv, const float* __restrict__ btab,
             float* __restrict__ ctx) {
    extern __shared__ float smf[];
    float* Qs = smf;
    float* Ks = Qs + 64*132;
    float* Vs = Ks + 64*68;
    float* Ps = Vs + 64*64;

    int tid = threadIdx.x;
    int q0 = blockIdx.x * BQ;
    int h = blockIdx.y, b = blockIdx.z;
    const float* base = qkv + (size_t)b * SS * (3*DD);
    int tx = tid & 15, ty = tid >> 4;

#pragma unroll
    for (int r = 0; r < 8; r++) {
        int i = tid + 256*r;
        int row = i >> 4, d4 = (i & 15) * 4;
        float4 qv = *(const float4*)(base + (size_t)(q0+row)*(3*DD) + h*HD + d4);
        Qs[(d4+0)*132+row] = qv.x; Qs[(d4+1)*132+row] = qv.y;
        Qs[(d4+2)*132+row] = qv.z; Qs[(d4+3)*132+row] = qv.w;
    }

    float o[8][4] = {};
    float m_i[8], l_i[8];
#pragma unroll
    for (int i = 0; i < 8; i++) { m_i[i] = -INFINITY; l_i[i] = 0.f; }

    for (int kt = 0; kt < SS/BK; kt++) {
        __syncthreads();
#pragma unroll
        for (int r = 0; r < 4; r++) {
            int i = tid + 256*r;
            int row = i >> 4, d4 = (i & 15) * 4;
            int kg = kt*BK + row;
            float4 kv = *(const float4*)(base + (size_t)kg*(3*DD) + DD + h*HD + d4);
            Ks[(d4+0)*68+row] = kv.x; Ks[(d4+1)*68+row] = kv.y;
            Ks[(d4+2)*68+row] = kv.z; Ks[(d4+3)*68+row] = kv.w;
            float4 vv = *(const float4*)(base + (size_t)kg*(3*DD) + 2*DD + h*HD + d4);
            *(float4*)&Vs[row*64 + d4] = vv;
        }
        __syncthreads();

        float s[8][4] = {};
#pragma unroll 4
        for (int dd = 0; dd < 64; dd++) {
            float a[8], bb[4];
#pragma unroll
            for (int i = 0; i < 8; i++) a[i] = Qs[dd*132 + ty*8 + i];
#pragma unroll
            for (int j = 0; j < 4; j++) bb[j] = Ks[dd*68 + tx*4 + j];
#pragma unroll
            for (int i = 0; i < 8; i++)
#pragma unroll
                for (int j = 0; j < 4; j++)
                    s[i][j] = fmaf(a[i], bb[j], s[i][j]);
        }

#pragma unroll
        for (int i = 0; i < 8; i++) {
            int qg = q0 + ty*8 + i;
            float mx = -INFINITY;
#pragma unroll
            for (int j = 0; j < 4; j++) {
                int kg = kt*BK + tx*4 + j;
                int dist = qg - kg; dist = dist < 0 ? -dist : dist;
                float sv = s[i][j]*0.125f + btab[dist];
                s[i][j] = sv;
                mx = fmaxf(mx, sv);
            }
#pragma unroll
            for (int o2 = 8; o2 > 0; o2 >>= 1)
                mx = fmaxf(mx, __shfl_xor_sync(0xffffffffu, mx, o2, 16));
            float newm = fmaxf(m_i[i], mx);
            float corr = __expf(m_i[i] - newm);
            float rs = 0.f;
            float p[4];
#pragma unroll
            for (int j = 0; j < 4; j++) { p[j] = __expf(s[i][j] - newm); rs += p[j]; }
#pragma unroll
            for (int o2 = 8; o2 > 0; o2 >>= 1)
                rs += __shfl_xor_sync(0xffffffffu, rs, o2, 16);
            l_i[i] = l_i[i]*corr + rs;
            m_i[i] = newm;
#pragma unroll
            for (int j = 0; j < 4; j++) o[i][j] *= corr;
#pragma unroll
            for (int j = 0; j < 4; j++) Ps[(tx*4+j)*132 + ty*8 + i] = p[j];
        }
        __syncthreads();

#pragma unroll 4
        for (int kk = 0; kk < 64; kk++) {
            float a[8], bb[4];
#pragma unroll
            for (int i = 0; i < 8; i++) a[i] = Ps[kk*132 + ty*8 + i];
#pragma unroll
            for (int j = 0; j < 4; j++) bb[j] = Vs[kk*64 + tx*4 + j];
#pragma unroll
            for (int i = 0; i < 8; i++)
#pragma unroll
                for (int j = 0; j < 4; j++)
                    o[i][j] = fmaf(a[i], bb[j], o[i][j]);
        }
    }

#pragma unroll
    for (int i = 0; i < 8; i++) {
        float inv = 1.f / l_i[i];
        int row = q0 + ty*8 + i;
#pragma unroll
        for (int j = 0; j < 4; j++)
            ctx[((size_t)b*SS + row)*DD + h*HD + tx*4 + j] = o[i][j] * inv;
    }
}

// ---------------- launcher --------------------------------------------------
extern "C" void kernel_launch(void* const* d_in, const int* in_sizes, int n_in,
                              void* d_out, int out_size) {
    const float* x      = (const float*)d_in[0];
    const float* w_qkv  = (const float*)d_in[1];
    const float* b_qkv  = (const float*)d_in[2];
    const float* w_out  = (const float*)d_in[3];
    const float* b_out  = (const float*)d_in[4];
    const float* gamma  = (const float*)d_in[5];
    const float* lnb    = (const float*)d_in[6];
    const float* beta   = (const float*)d_in[7];
    float* out = (float*)d_out;

    float *xn, *qkv, *ctx, *btab, *wtq, *wto;
    cudaGetSymbolAddress((void**)&xn,   g_xn);
    cudaGetSymbolAddress((void**)&qkv,  g_qkv);
    cudaGetSymbolAddress((void**)&ctx,  g_ctx);
    cudaGetSymbolAddress((void**)&btab, g_btab);
    cudaGetSymbolAddress((void**)&wtq,  g_wtq);
    cudaGetSymbolAddress((void**)&wto,  g_wto);

    cudaFuncSetAttribute(flash_kernel,
                         cudaFuncAttributeMaxDynamicSharedMemorySize, FLASH_SMEM);

    transpose_kernel<<<dim3(3*DD/32, DD/32), dim3(32,8)>>>(w_qkv, wtq, DD, 3*DD);
    transpose_kernel<<<dim3(DD/32,   DD/32), dim3(32,8)>>>(w_out, wto, DD, DD);
    ln_kernel<<<ROWS, 256>>>(x, gamma, lnb, xn);
    bias_kernel<<<(SS+255)/256, 256>>>(beta, btab);

    gemm_bf16x3<false><<<dim3(3*DD/128, ROWS/128), 256>>>(
        xn, wtq, b_qkv, nullptr, qkv, 3*DD);
    flash_kernel<<<dim3(SS/BQ, NH, BB), 256, FLASH_SMEM>>>(qkv, btab, ctx);
    gemm_bf16x3<true><<<dim3(DD/128, ROWS/128), 256>>>(
        ctx, wto, b_out, x, out, DD);
}

// round 4
// speedup vs baseline: 1.8157x; 1.3341x over previous
#include <cuda_runtime.h>
#include <cuda_bf16.h>
#include <math.h>
#include <stdint.h>

#define BB 2
#define SS 2048
#define DD 1024
#define NH 16
#define HD 64
#define ROWS (BB*SS)          // 4096
#define GK DD                 // 1024

// ---------------- scratch (static device globals: no allocation) ------------
__device__ float g_xn[ROWS*DD];          // 16 MB
__device__ float g_qkv[ROWS*3*DD];       // 48 MB
__device__ float g_ctx[ROWS*DD];         // 16 MB
__device__ float g_btab[SS];             // 8 KB
__device__ float g_wtq[3*DD*DD];         // 12 MB: w_qkv transposed [N,K]
__device__ float g_wto[DD*DD];           // 4 MB : w_out transposed [N,K]

// ---------------- LayerNorm ------------------------------------------------
__global__ void ln_kernel(const float* __restrict__ x,
                          const float* __restrict__ gamma,
                          const float* __restrict__ lnb,
                          float* __restrict__ out) {
    int row = blockIdx.x;
    const float* xr = x + (size_t)row * DD;
    float v[4];
    float s = 0.f;
#pragma unroll
    for (int i = 0; i < 4; i++) { v[i] = xr[threadIdx.x + 256*i]; s += v[i]; }
    __shared__ float red[8];
#pragma unroll
    for (int o = 16; o > 0; o >>= 1) s += __shfl_xor_sync(0xffffffffu, s, o);
    if ((threadIdx.x & 31) == 0) red[threadIdx.x >> 5] = s;
    __syncthreads();
    float tot = 0.f;
#pragma unroll
    for (int i = 0; i < 8; i++) tot += red[i];
    float mean = tot * (1.f/DD);
    float vs = 0.f;
#pragma unroll
    for (int i = 0; i < 4; i++) { float d = v[i]-mean; vs += d*d; }
    __syncthreads();
#pragma unroll
    for (int o = 16; o > 0; o >>= 1) vs += __shfl_xor_sync(0xffffffffu, vs, o);
    if ((threadIdx.x & 31) == 0) red[threadIdx.x >> 5] = vs;
    __syncthreads();
    float vtot = 0.f;
#pragma unroll
    for (int i = 0; i < 8; i++) vtot += red[i];
    float rstd = rsqrtf(vtot*(1.f/DD) + 1e-5f);
    float* orow = out + (size_t)row * DD;
#pragma unroll
    for (int i = 0; i < 4; i++) {
        int c = threadIdx.x + 256*i;
        orow[c] = (v[i]-mean)*rstd*gamma[c] + lnb[c];
    }
}

__global__ void bias_kernel(const float* __restrict__ beta, float* __restrict__ tab) {
    int i = blockIdx.x*256 + threadIdx.x;
    if (i < SS) tab[i] = beta[0] * log1pf((float)i);
}

// ---------------- weight transpose: in[K][N] -> out[N][K] -------------------
__global__ void transpose_kernel(const float* __restrict__ in, float* __restrict__ out,
                                 int K, int N) {
    __shared__ float t[32][33];
    int n0 = blockIdx.x*32, k0 = blockIdx.y*32;
    int tx = threadIdx.x, ty = threadIdx.y;   // 32 x 8
#pragma unroll
    for (int i = 0; i < 32; i += 8)
        t[ty+i][tx] = in[(size_t)(k0+ty+i)*N + n0+tx];
    __syncthreads();
#pragma unroll
    for (int i = 0; i < 32; i += 8)
        out[(size_t)(n0+ty+i)*K + k0+tx] = t[tx][ty+i];
}

// =================== shared helpers ========================================
__device__ __forceinline__ uint32_t bf16x2_hi(float x0, float x1,
                                              float& r0, float& r1) {
    __nv_bfloat16 h0 = __float2bfloat16_rn(x0);
    __nv_bfloat16 h1 = __float2bfloat16_rn(x1);
    r0 = x0 - __bfloat162float(h0);
    r1 = x1 - __bfloat162float(h1);
    return ((uint32_t)__bfloat16_as_ushort(h1) << 16) | __bfloat16_as_ushort(h0);
}
__device__ __forceinline__ uint32_t bf16x2_of(float x0, float x1) {
    __nv_bfloat16 h0 = __float2bfloat16_rn(x0);
    __nv_bfloat16 h1 = __float2bfloat16_rn(x1);
    return ((uint32_t)__bfloat16_as_ushort(h1) << 16) | __bfloat16_as_ushort(h0);
}

#define MMA_BF16(d, a, b) \
    asm volatile("mma.sync.aligned.m16n8k16.row.col.f32.bf16.bf16.f32 " \
        "{%0,%1,%2,%3}, {%4,%5,%6,%7}, {%8,%9}, {%0,%1,%2,%3};" \
        : "+f"((d)[0]), "+f"((d)[1]), "+f"((d)[2]), "+f"((d)[3]) \
        : "r"((a).x), "r"((a).y), "r"((a).z), "r"((a).w), \
          "r"((b).x), "r"((b).y))

// fast FFMA-only exp (x <= 0 expected; valid for x >= ~-80, clamped)
__device__ __forceinline__ float fexp(float x) {
    x = fmaxf(x, -80.f);
    float t = fmaf(x, 1.4426950408889634f, 12582912.0f);
    int n = __float_as_int(t) - 0x4B400000;
    float tm = t - 12582912.0f;
    float f = fmaf(x, 1.4426950408889634f, -tm);
    float p = 0.0013333558f;
    p = fmaf(p, f, 0.0096181291f);
    p = fmaf(p, f, 0.0555041087f);
    p = fmaf(p, f, 0.2402265070f);
    p = fmaf(p, f, 0.6931471806f);
    p = fmaf(p, f, 1.0f);
    return __int_as_float(__float_as_int(p) + (n << 23));
}

// =================== split-bf16 mma.sync GEMM (unchanged, passing) ==========
template<bool RESID>
__global__ void __launch_bounds__(256)
gemm_bf16x3(const float* __restrict__ A, const float* __restrict__ Bt,
            const float* __restrict__ bias, const float* __restrict__ resid,
            float* __restrict__ C, int N) {
    __shared__ uint4 AfH[2][8][32];
    __shared__ uint4 AfL[2][8][32];
    __shared__ uint2 BfH[2][16][32];
    __shared__ uint2 BfL[2][16][32];

    int tid = threadIdx.x, lane = tid & 31, wid = tid >> 5;
    int bm = blockIdx.y * 128, bn = blockIdx.x * 128;
    int wm = wid >> 1, wn = wid & 1;

    const float* Ag = A  + (size_t)bm * GK;
    const float* Bg = Bt + (size_t)bn * GK;

    float acc[2][8][4] = {};

    for (int c = 0; c < GK/32; c++) {
#pragma unroll
        for (int r = 0; r < 4; r++) {
            int i = tid + 256*r;
            int row = i >> 3, f4 = i & 7;
            int s  = f4 >> 2;
            int cc = (f4 & 3) * 4;
            int t0 = (cc & 7) >> 1;
            {
                float4 av = *(const float4*)(Ag + (size_t)row*GK + c*32 + f4*4);
                float l0, l1, l2, l3;
                uint32_t h01 = bf16x2_hi(av.x, av.y, l0, l1);
                uint32_t h23 = bf16x2_hi(av.z, av.w, l2, l3);
                uint32_t lo01 = bf16x2_of(l0, l1);
                uint32_t lo23 = bf16x2_of(l2, l3);
                int rr = row & 15, mt = row >> 4;
                int slot = (cc < 8 ? 0 : 2) + (rr >> 3);
                int base = ((s*8 + mt)*32)*4;
                int i0 = base + ((rr & 7)*4 + t0)*4 + slot;
                int i1 = base + ((rr & 7)*4 + t0 + 1)*4 + slot;
                ((uint32_t*)AfH)[i0] = h01;
                ((uint32_t*)AfH)[i1] = h23;
                ((uint32_t*)AfL)[i0] = lo01;
                ((uint32_t*)AfL)[i1] = lo23;
            }
            {
                float4 bv = *(const float4*)(Bg + (size_t)row*GK + c*32 + f4*4);
                float l0, l1, l2, l3;
                uint32_t h01 = bf16x2_hi(bv.x, bv.y, l0, l1);
                uint32_t h23 = bf16x2_hi(bv.z, bv.w, l2, l3);
                uint32_t lo01 = bf16x2_of(l0, l1);
                uint32_t lo23 = bf16x2_of(l2, l3);
                int nt = row >> 3;
                int slot = (cc < 8) ? 0 : 1;
                int base = ((s*16 + nt)*32)*2;
                int i0 = base + ((row & 7)*4 + t0)*2 + slot;
                int i1 = base + ((row & 7)*4 + t0 + 1)*2 + slot;
                ((uint32_t*)BfH)[i0] = h01;
                ((uint32_t*)BfH)[i1] = h23;
                ((uint32_t*)BfL)[i0] = lo01;
                ((uint32_t*)BfL)[i1] = lo23;
            }
        }
        __syncthreads();
#pragma unroll
        for (int s = 0; s < 2; s++) {
            uint4 ah[2], al[2];
#pragma unroll
            for (int mi = 0; mi < 2; mi++) {
                ah[mi] = AfH[s][wm*2 + mi][lane];
                al[mi] = AfL[s][wm*2 + mi][lane];
            }
#pragma unroll
            for (int ni = 0; ni < 8; ni++) {
                uint2 bh = BfH[s][wn*8 + ni][lane];
                uint2 bl = BfL[s][wn*8 + ni][lane];
#pragma unroll
                for (int mi = 0; mi < 2; mi++) {
                    MMA_BF16(acc[mi][ni], ah[mi], bh);
                    MMA_BF16(acc[mi][ni], ah[mi], bl);
                    MMA_BF16(acc[mi][ni], al[mi], bh);
                }
            }
        }
        __syncthreads();
    }

    int g = lane >> 2, tq = lane & 3;
#pragma unroll
    for (int mi = 0; mi < 2; mi++) {
#pragma unroll
        for (int half = 0; half < 2; half++) {
            int row = bm + (wm*2 + mi)*16 + g + half*8;
            float* crow = C + (size_t)row * N;
            const float* rrow = resid + (size_t)row * N;
#pragma unroll
            for (int ni = 0; ni < 8; ni++) {
                int col = bn + (wn*8 + ni)*8 + tq*2;
                float2 v;
                v.x = acc[mi][ni][half*2 + 0] + bias[col];
                v.y = acc[mi][ni][half*2 + 1] + bias[col + 1];
                if (RESID) {
                    v.x += rrow[col];
                    v.y += rrow[col + 1];
                }
                *(float2*)(crow + col) = v;
            }
        }
    }
}

// =================== mma-based flash attention ==============================
// grid (SS/128, NH, BB), 256 thr = 8 warps; warp w owns q rows [w*16, w*16+16).
// K-tile = 64 keys. Q fragments in regs; K/V staged as bf16 h/l fragments.
__global__ void __launch_bounds__(256)
flash_mma(const float* __restrict__ qkv, const float* __restrict__ btab,
          float* __restrict__ ctx) {
    __shared__ uint2 KhS[4][8][32];       // [kstep(d)][ntile(key)][lane]
    __shared__ uint2 KlS[4][8][32];
    __shared__ unsigned short VhS[4*8*32*4];  // [kstep(key)][ntile(d)][lane][j]
    __shared__ unsigned short VlS[4*8*32*4];
    __shared__ float bt[SS];

    int tid = threadIdx.x, lane = tid & 31, w = tid >> 5;
    int g = lane >> 2, tq = lane & 3;
    int q0 = blockIdx.x * 128;
    int h = blockIdx.y, b = blockIdx.z;
    const float* base = qkv + (size_t)b * SS * (3*DD);

    // cache bias table
#pragma unroll
    for (int i = 0; i < SS/256; i++) bt[tid + 256*i] = btab[tid + 256*i];

    // ---- build Q fragments in registers (once) ----
    int qr0 = q0 + w*16 + g, qr1 = qr0 + 8;
    const float* qp0 = base + (size_t)qr0*(3*DD) + h*HD;
    const float* qp1 = base + (size_t)qr1*(3*DD) + h*HD;
    uint4 qh[4], ql[4];
#pragma unroll
    for (int s = 0; s < 4; s++) {
        int c0 = s*16 + 2*tq;
        float2 x0 = *(const float2*)(qp0 + c0);
        float2 x1 = *(const float2*)(qp1 + c0);
        float2 x2 = *(const float2*)(qp0 + c0 + 8);
        float2 x3 = *(const float2*)(qp1 + c0 + 8);
        float r0, r1;
        qh[s].x = bf16x2_hi(x0.x, x0.y, r0, r1); ql[s].x = bf16x2_of(r0, r1);
        qh[s].y = bf16x2_hi(x1.x, x1.y, r0, r1); ql[s].y = bf16x2_of(r0, r1);
        qh[s].z = bf16x2_hi(x2.x, x2.y, r0, r1); ql[s].z = bf16x2_of(r0, r1);
        qh[s].w = bf16x2_hi(x3.x, x3.y, r0, r1); ql[s].w = bf16x2_of(r0, r1);
    }

    float oacc[8][4] = {};
    float m0 = -INFINITY, m1 = -INFINITY, l0 = 0.f, l1 = 0.f;

    for (int kt = 0; kt < SS/64; kt++) {
        __syncthreads();
        // ---- stage K,V (64x64 each) into fragment smem ----
#pragma unroll
        for (int r = 0; r < 4; r++) {
            int i = tid + 256*r;          // 0..1023
            int row = i >> 4, f4 = i & 15;
            int kg = kt*64 + row;
            // K: B-operand frag, n = key, k-dim = d
            {
                float4 kv = *(const float4*)(base + (size_t)kg*(3*DD) + DD + h*HD + f4*4);
                int s = f4 >> 2, cc = (f4 & 3)*4;
                int t0 = (cc & 7) >> 1, slot = (cc < 8) ? 0 : 1;
                int gg = row & 7, nt = row >> 3;
                float r0_, r1_, r2_, r3_;
                uint32_t h01 = bf16x2_hi(kv.x, kv.y, r0_, r1_);
                uint32_t h23 = bf16x2_hi(kv.z, kv.w, r2_, r3_);
                uint32_t lo01 = bf16x2_of(r0_, r1_);
                uint32_t lo23 = bf16x2_of(r2_, r3_);
                int bidx = ((s*8 + nt)*32)*2;
                int i0 = bidx + (gg*4 + t0)*2 + slot;
                int i1 = bidx + (gg*4 + t0 + 1)*2 + slot;
                ((uint32_t*)KhS)[i0] = h01; ((uint32_t*)KhS)[i1] = h23;
                ((uint32_t*)KlS)[i0] = lo01; ((uint32_t*)KlS)[i1] = lo23;
            }
            // V: B-operand frag, n = d, k-dim = key (transposed staging)
            {
                float4 vv = *(const float4*)(base + (size_t)kg*(3*DD) + 2*DD + h*HD + f4*4);
                int s2 = row >> 4, r2 = row & 15;
                int tq2 = (r2 & 7) >> 1;
                int j = ((r2 >= 8) ? 2 : 0) + (r2 & 1);
                float vals[4] = {vv.x, vv.y, vv.z, vv.w};
#pragma unroll
                for (int e = 0; e < 4; e++) {
                    int d = f4*4 + e;
                    int nt2 = d >> 3, g2 = d & 7;
                    int idx = ((s2*8 + nt2)*32 + g2*4 + tq2)*4 + j;
                    __nv_bfloat16 hv = __float2bfloat16_rn(vals[e]);
                    VhS[idx] = __bfloat16_as_ushort(hv);
                    VlS[idx] = __bfloat16_as_ushort(
                        __float2bfloat16_rn(vals[e] - __bfloat162float(hv)));
                }
            }
        }
        __syncthreads();

        // ---- S = Q @ K^T (3-pass split bf16) ----
        float sacc[8][4] = {};
#pragma unroll
        for (int s = 0; s < 4; s++) {
#pragma unroll
            for (int nt = 0; nt < 8; nt++) {
                uint2 kh = KhS[s][nt][lane];
                uint2 kl = KlS[s][nt][lane];
                MMA_BF16(sacc[nt], qh[s], kh);
                MMA_BF16(sacc[nt], qh[s], kl);
                MMA_BF16(sacc[nt], ql[s], kh);
            }
        }

        // ---- scale + bias + online softmax ----
        int ktbase = kt*64;
        float mx0 = -INFINITY, mx1 = -INFINITY;
#pragma unroll
        for (int nt = 0; nt < 8; nt++) {
            int keyb = ktbase + nt*8 + 2*tq;
#pragma unroll
            for (int jj = 0; jj < 2; jj++) {
                int key = keyb + jj;
                int d0 = qr0 - key; d0 = d0 < 0 ? -d0 : d0;
                int d1 = qr1 - key; d1 = d1 < 0 ? -d1 : d1;
                float v0 = fmaf(sacc[nt][jj],   0.125f, bt[d0]);
                float v1 = fmaf(sacc[nt][2+jj], 0.125f, bt[d1]);
                sacc[nt][jj] = v0;   mx0 = fmaxf(mx0, v0);
                sacc[nt][2+jj] = v1; mx1 = fmaxf(mx1, v1);
            }
        }
        mx0 = fmaxf(mx0, __shfl_xor_sync(0xffffffffu, mx0, 1));
        mx0 = fmaxf(mx0, __shfl_xor_sync(0xffffffffu, mx0, 2));
        mx1 = fmaxf(mx1, __shfl_xor_sync(0xffffffffu, mx1, 1));
        mx1 = fmaxf(mx1, __shfl_xor_sync(0xffffffffu, mx1, 2));
        float newm0 = fmaxf(m0, mx0), newm1 = fmaxf(m1, mx1);
        float corr0 = fexp(m0 - newm0), corr1 = fexp(m1 - newm1);
        float rs0 = 0.f, rs1 = 0.f;
#pragma unroll
        for (int nt = 0; nt < 8; nt++) {
#pragma unroll
            for (int jj = 0; jj < 2; jj++) {
                float p0 = fexp(sacc[nt][jj]   - newm0);
                float p1 = fexp(sacc[nt][2+jj] - newm1);
                sacc[nt][jj] = p0;   rs0 += p0;
                sacc[nt][2+jj] = p1; rs1 += p1;
            }
        }
        rs0 += __shfl_xor_sync(0xffffffffu, rs0, 1);
        rs0 += __shfl_xor_sync(0xffffffffu, rs0, 2);
        rs1 += __shfl_xor_sync(0xffffffffu, rs1, 1);
        rs1 += __shfl_xor_sync(0xffffffffu, rs1, 2);
        l0 = l0*corr0 + rs0; m0 = newm0;
        l1 = l1*corr1 + rs1; m1 = newm1;
#pragma unroll
        for (int nt = 0; nt < 8; nt++) {
            oacc[nt][0] *= corr0; oacc[nt][1] *= corr0;
            oacc[nt][2] *= corr1; oacc[nt][3] *= corr1;
        }

        // ---- O += P @ V (3-pass split bf16); P frags built from sacc ----
#pragma unroll
        for (int s = 0; s < 4; s++) {
            uint4 pah, pal;
            float r0_, r1_;
            pah.x = bf16x2_hi(sacc[2*s][0],   sacc[2*s][1],   r0_, r1_);
            pal.x = bf16x2_of(r0_, r1_);
            pah.y = bf16x2_hi(sacc[2*s][2],   sacc[2*s][3],   r0_, r1_);
            pal.y = bf16x2_of(r0_, r1_);
            pah.z = bf16x2_hi(sacc[2*s+1][0], sacc[2*s+1][1], r0_, r1_);
            pal.z = bf16x2_of(r0_, r1_);
            pah.w = bf16x2_hi(sacc[2*s+1][2], sacc[2*s+1][3], r0_, r1_);
            pal.w = bf16x2_of(r0_, r1_);
#pragma unroll
            for (int nt = 0; nt < 8; nt++) {
                uint2 vh = *(uint2*)&VhS[((s*8 + nt)*32 + lane)*4];
                uint2 vl = *(uint2*)&VlS[((s*8 + nt)*32 + lane)*4];
                MMA_BF16(oacc[nt], pah, vh);
                MMA_BF16(oacc[nt], pah, vl);
                MMA_BF16(oacc[nt], pal, vh);
            }
        }
    }

    // ---- write ctx ----
    float inv0 = 1.f / l0, inv1 = 1.f / l1;
    float* c0 = ctx + ((size_t)b*SS + qr0)*DD + h*HD;
    float* c1 = ctx + ((size_t)b*SS + qr1)*DD + h*HD;
#pragma unroll
    for (int nt = 0; nt < 8; nt++) {
        int d = nt*8 + 2*tq;
        float2 v0 = { oacc[nt][0]*inv0, oacc[nt][1]*inv0 };
        float2 v1 = { oacc[nt][2]*inv1, oacc[nt][3]*inv1 };
        *(float2*)(c0 + d) = v0;
        *(float2*)(c1 + d) = v1;
    }
}

// ---------------- launcher --------------------------------------------------
extern "C" void kernel_launch(void* const* d_in, const int* in_sizes, int n_in,
                              void* d_out, int out_size) {
    const float* x      = (const float*)d_in[0];
    const float* w_qkv  = (const float*)d_in[1];
    const float* b_qkv  = (const float*)d_in[2];
    const float* w_out  = (const float*)d_in[3];
    const float* b_out  = (const float*)d_in[4];
    const float* gamma  = (const float*)d_in[5];
    const float* lnb    = (const float*)d_in[6];
    const float* beta   = (const float*)d_in[7];
    float* out = (float*)d_out;

    float *xn, *qkv, *ctx, *btab, *wtq, *wto;
    cudaGetSymbolAddress((void**)&xn,   g_xn);
    cudaGetSymbolAddress((void**)&qkv,  g_qkv);
    cudaGetSymbolAddress((void**)&ctx,  g_ctx);
    cudaGetSymbolAddress((void**)&btab, g_btab);
    cudaGetSymbolAddress((void**)&wtq,  g_wtq);
    cudaGetSymbolAddress((void**)&wto,  g_wto);

    transpose_kernel<<<dim3(3*DD/32, DD/32), dim3(32,8)>>>(w_qkv, wtq, DD, 3*DD);
    transpose_kernel<<<dim3(DD/32,   DD/32), dim3(32,8)>>>(w_out, wto, DD, DD);
    ln_kernel<<<ROWS, 256>>>(x, gamma, lnb, xn);
    bias_kernel<<<(SS+255)/256, 256>>>(beta, btab);

    gemm_bf16x3<false><<<dim3(3*DD/128, ROWS/128), 256>>>(
        xn, wtq, b_qkv, nullptr, qkv, 3*DD);
    flash_mma<<<dim3(SS/128, NH, BB), 256>>>(qkv, btab, ctx);
    gemm_bf16x3<true><<<dim3(DD/128, ROWS/128), 256>>>(
        ctx, wto, b_out, x, out, DD);
}

// round 6
// speedup vs baseline: 2.4676x; 1.3591x over previous
#include <cuda_runtime.h>
#include <cuda_bf16.h>
#include <math.h>
#include <stdint.h>

#define BB 2
#define SS 2048
#define DD 1024
#define NH 16
#define HD 64
#define ROWS (BB*SS)          // 4096
#define GK DD                 // 1024

// ---------------- scratch (static device globals: no allocation) ------------
__device__ float g_xn[ROWS*DD];          // 16 MB
__device__ float g_qkv[ROWS*3*DD];       // 48 MB
__device__ float g_ctx[ROWS*DD];         // 16 MB
__device__ float g_btab[SS];             // 8 KB
__device__ float g_wtq[3*DD*DD];         // 12 MB: w_qkv transposed [N,K]
__device__ float g_wto[DD*DD];           // 4 MB : w_out transposed [N,K]

// ---------------- LayerNorm ------------------------------------------------
__global__ void ln_kernel(const float* __restrict__ x,
                          const float* __restrict__ gamma,
                          const float* __restrict__ lnb,
                          float* __restrict__ out) {
    int row = blockIdx.x;
    const float* xr = x + (size_t)row * DD;
    float v[4];
    float s = 0.f;
#pragma unroll
    for (int i = 0; i < 4; i++) { v[i] = xr[threadIdx.x + 256*i]; s += v[i]; }
    __shared__ float red[8];
#pragma unroll
    for (int o = 16; o > 0; o >>= 1) s += __shfl_xor_sync(0xffffffffu, s, o);
    if ((threadIdx.x & 31) == 0) red[threadIdx.x >> 5] = s;
    __syncthreads();
    float tot = 0.f;
#pragma unroll
    for (int i = 0; i < 8; i++) tot += red[i];
    float mean = tot * (1.f/DD);
    float vs = 0.f;
#pragma unroll
    for (int i = 0; i < 4; i++) { float d = v[i]-mean; vs += d*d; }
    __syncthreads();
#pragma unroll
    for (int o = 16; o > 0; o >>= 1) vs += __shfl_xor_sync(0xffffffffu, vs, o);
    if ((threadIdx.x & 31) == 0) red[threadIdx.x >> 5] = vs;
    __syncthreads();
    float vtot = 0.f;
#pragma unroll
    for (int i = 0; i < 8; i++) vtot += red[i];
    float rstd = rsqrtf(vtot*(1.f/DD) + 1e-5f);
    float* orow = out + (size_t)row * DD;
#pragma unroll
    for (int i = 0; i < 4; i++) {
        int c = threadIdx.x + 256*i;
        orow[c] = (v[i]-mean)*rstd*gamma[c] + lnb[c];
    }
}

__global__ void bias_kernel(const float* __restrict__ beta, float* __restrict__ tab) {
    int i = blockIdx.x*256 + threadIdx.x;
    if (i < SS) tab[i] = beta[0] * log1pf((float)i);
}

// ---------------- weight transpose: in[K][N] -> out[N][K] -------------------
__global__ void transpose_kernel(const float* __restrict__ in, float* __restrict__ out,
                                 int K, int N) {
    __shared__ float t[32][33];
    int n0 = blockIdx.x*32, k0 = blockIdx.y*32;
    int tx = threadIdx.x, ty = threadIdx.y;   // 32 x 8
#pragma unroll
    for (int i = 0; i < 32; i += 8)
        t[ty+i][tx] = in[(size_t)(k0+ty+i)*N + n0+tx];
    __syncthreads();
#pragma unroll
    for (int i = 0; i < 32; i += 8)
        out[(size_t)(n0+ty+i)*K + k0+tx] = t[tx][ty+i];
}

// =================== shared helpers ========================================
__device__ __forceinline__ uint32_t bf16x2_hi(float x0, float x1,
                                              float& r0, float& r1) {
    __nv_bfloat16 h0 = __float2bfloat16_rn(x0);
    __nv_bfloat16 h1 = __float2bfloat16_rn(x1);
    r0 = x0 - __bfloat162float(h0);
    r1 = x1 - __bfloat162float(h1);
    return ((uint32_t)__bfloat16_as_ushort(h1) << 16) | __bfloat16_as_ushort(h0);
}
__device__ __forceinline__ uint32_t bf16x2_of(float x0, float x1) {
    __nv_bfloat16 h0 = __float2bfloat16_rn(x0);
    __nv_bfloat16 h1 = __float2bfloat16_rn(x1);
    return ((uint32_t)__bfloat16_as_ushort(h1) << 16) | __bfloat16_as_ushort(h0);
}

#define MMA_BF16(d, a, b) \
    asm volatile("mma.sync.aligned.m16n8k16.row.col.f32.bf16.bf16.f32 " \
        "{%0,%1,%2,%3}, {%4,%5,%6,%7}, {%8,%9}, {%0,%1,%2,%3};" \
        : "+f"((d)[0]), "+f"((d)[1]), "+f"((d)[2]), "+f"((d)[3]) \
        : "r"((a).x), "r"((a).y), "r"((a).z), "r"((a).w), \
          "r"((b).x), "r"((b).y))

#define LDSM2(r0, r1, a) \
    asm volatile("ldmatrix.sync.aligned.m8n8.x2.shared.b16 {%0,%1}, [%2];" \
        : "=r"(r0), "=r"(r1) : "r"(a))
#define LDSM2T(r0, r1, a) \
    asm volatile("ldmatrix.sync.aligned.m8n8.x2.trans.shared.b16 {%0,%1}, [%2];" \
        : "=r"(r0), "=r"(r1) : "r"(a))

// fast FFMA-only exp (x <= 0 expected; valid for x >= ~-80, clamped)
__device__ __forceinline__ float fexp(float x) {
    x = fmaxf(x, -80.f);
    float t = fmaf(x, 1.4426950408889634f, 12582912.0f);
    int n = __float_as_int(t) - 0x4B400000;
    float tm = t - 12582912.0f;
    float f = fmaf(x, 1.4426950408889634f, -tm);
    float p = 0.0013333558f;
    p = fmaf(p, f, 0.0096181291f);
    p = fmaf(p, f, 0.0555041087f);
    p = fmaf(p, f, 0.2402265070f);
    p = fmaf(p, f, 0.6931471806f);
    p = fmaf(p, f, 1.0f);
    return __int_as_float(__float_as_int(p) + (n << 23));
}

// =================== split-bf16 mma.sync GEMM (unchanged, passing) ==========
template<bool RESID>
__global__ void __launch_bounds__(256)
gemm_bf16x3(const float* __restrict__ A, const float* __restrict__ Bt,
            const float* __restrict__ bias, const float* __restrict__ resid,
            float* __restrict__ C, int N) {
    __shared__ uint4 AfH[2][8][32];
    __shared__ uint4 AfL[2][8][32];
    __shared__ uint2 BfH[2][16][32];
    __shared__ uint2 BfL[2][16][32];

    int tid = threadIdx.x, lane = tid & 31, wid = tid >> 5;
    int bm = blockIdx.y * 128, bn = blockIdx.x * 128;
    int wm = wid >> 1, wn = wid & 1;

    const float* Ag = A  + (size_t)bm * GK;
    const float* Bg = Bt + (size_t)bn * GK;

    float acc[2][8][4] = {};

    for (int c = 0; c < GK/32; c++) {
#pragma unroll
        for (int r = 0; r < 4; r++) {
            int i = tid + 256*r;
            int row = i >> 3, f4 = i & 7;
            int s  = f4 >> 2;
            int cc = (f4 & 3) * 4;
            int t0 = (cc & 7) >> 1;
            {
                float4 av = *(const float4*)(Ag + (size_t)row*GK + c*32 + f4*4);
                float l0, l1, l2, l3;
                uint32_t h01 = bf16x2_hi(av.x, av.y, l0, l1);
                uint32_t h23 = bf16x2_hi(av.z, av.w, l2, l3);
                uint32_t lo01 = bf16x2_of(l0, l1);
                uint32_t lo23 = bf16x2_of(l2, l3);
                int rr = row & 15, mt = row >> 4;
                int slot = (cc < 8 ? 0 : 2) + (rr >> 3);
                int base = ((s*8 + mt)*32)*4;
                int i0 = base + ((rr & 7)*4 + t0)*4 + slot;
                int i1 = base + ((rr & 7)*4 + t0 + 1)*4 + slot;
                ((uint32_t*)AfH)[i0] = h01;
                ((uint32_t*)AfH)[i1] = h23;
                ((uint32_t*)AfL)[i0] = lo01;
                ((uint32_t*)AfL)[i1] = lo23;
            }
            {
                float4 bv = *(const float4*)(Bg + (size_t)row*GK + c*32 + f4*4);
                float l0, l1, l2, l3;
                uint32_t h01 = bf16x2_hi(bv.x, bv.y, l0, l1);
                uint32_t h23 = bf16x2_hi(bv.z, bv.w, l2, l3);
                uint32_t lo01 = bf16x2_of(l0, l1);
                uint32_t lo23 = bf16x2_of(l2, l3);
                int nt = row >> 3;
                int slot = (cc < 8) ? 0 : 1;
                int base = ((s*16 + nt)*32)*2;
                int i0 = base + ((row & 7)*4 + t0)*2 + slot;
                int i1 = base + ((row & 7)*4 + t0 + 1)*2 + slot;
                ((uint32_t*)BfH)[i0] = h01;
                ((uint32_t*)BfH)[i1] = h23;
                ((uint32_t*)BfL)[i0] = lo01;
                ((uint32_t*)BfL)[i1] = lo23;
            }
        }
        __syncthreads();
#pragma unroll
        for (int s = 0; s < 2; s++) {
            uint4 ah[2], al[2];
#pragma unroll
            for (int mi = 0; mi < 2; mi++) {
                ah[mi] = AfH[s][wm*2 + mi][lane];
                al[mi] = AfL[s][wm*2 + mi][lane];
            }
#pragma unroll
            for (int ni = 0; ni < 8; ni++) {
                uint2 bh = BfH[s][wn*8 + ni][lane];
                uint2 bl = BfL[s][wn*8 + ni][lane];
#pragma unroll
                for (int mi = 0; mi < 2; mi++) {
                    MMA_BF16(acc[mi][ni], ah[mi], bh);
                    MMA_BF16(acc[mi][ni], ah[mi], bl);
                    MMA_BF16(acc[mi][ni], al[mi], bh);
                }
            }
        }
        __syncthreads();
    }

    int g = lane >> 2, tq = lane & 3;
#pragma unroll
    for (int mi = 0; mi < 2; mi++) {
#pragma unroll
        for (int half = 0; half < 2; half++) {
            int row = bm + (wm*2 + mi)*16 + g + half*8;
            float* crow = C + (size_t)row * N;
            const float* rrow = resid + (size_t)row * N;
#pragma unroll
            for (int ni = 0; ni < 8; ni++) {
                int col = bn + (wn*8 + ni)*8 + tq*2;
                float2 v;
                v.x = acc[mi][ni][half*2 + 0] + bias[col];
                v.y = acc[mi][ni][half*2 + 1] + bias[col + 1];
                if (RESID) {
                    v.x += rrow[col];
                    v.y += rrow[col + 1];
                }
                *(float2*)(crow + col) = v;
            }
        }
    }
}

// =================== mma flash attention (ldmatrix staging) =================
// grid (SS/128, NH, BB), 256 thr = 8 warps; warp w owns q rows [w*16, w*16+16).
// K-tile = 64 keys. K (hi+lo) and V (hi) staged as row-major bf16 [key][72].
#define KVSTR 72   // padded stride in bf16 elems (144 B: conflict-free ldmatrix)

__global__ void __launch_bounds__(256)
flash_mma(const float* __restrict__ qkv, const float* __restrict__ btab,
          float* __restrict__ ctx) {
    __shared__ unsigned short KhS[64*KVSTR];
    __shared__ unsigned short KlS[64*KVSTR];
    __shared__ unsigned short VhS[64*KVSTR];
    __shared__ float bt[SS];

    int tid = threadIdx.x, lane = tid & 31, w = tid >> 5;
    int g = lane >> 2, tq = lane & 3;
    int q0 = blockIdx.x * 128;
    int h = blockIdx.y, b = blockIdx.z;
    const float* base = qkv + (size_t)b * SS * (3*DD);

    // cache bias table
#pragma unroll
    for (int i = 0; i < SS/256; i++) bt[tid + 256*i] = btab[tid + 256*i];

    // per-lane ldmatrix base offsets (bytes)
    uint32_t KhB = (uint32_t)__cvta_generic_to_shared(KhS);
    uint32_t KlB = (uint32_t)__cvta_generic_to_shared(KlS);
    uint32_t VhB = (uint32_t)__cvta_generic_to_shared(VhS);
    // K fragment rows: key = nt*8 + (lane&7); d-offset = s*16 + ((lane&8)?8:0)
    uint32_t aKh = KhB + 2*((lane & 7)*KVSTR + ((lane & 8) ? 8 : 0));
    uint32_t aKl = KlB + 2*((lane & 7)*KVSTR + ((lane & 8) ? 8 : 0));
    // V fragment rows (trans): key = s2*16 + (lane&15); d-offset = nt*8
    uint32_t aVh = VhB + 2*((lane & 15)*KVSTR);

    // ---- build Q fragments in registers (once) ----
    int qr0 = q0 + w*16 + g, qr1 = qr0 + 8;
    const float* qp0 = base + (size_t)qr0*(3*DD) + h*HD;
    const float* qp1 = base + (size_t)qr1*(3*DD) + h*HD;
    uint4 qh[4], ql[4];
#pragma unroll
    for (int s = 0; s < 4; s++) {
        int c0 = s*16 + 2*tq;
        float2 x0 = *(const float2*)(qp0 + c0);
        float2 x1 = *(const float2*)(qp1 + c0);
        float2 x2 = *(const float2*)(qp0 + c0 + 8);
        float2 x3 = *(const float2*)(qp1 + c0 + 8);
        float r0, r1;
        qh[s].x = bf16x2_hi(x0.x, x0.y, r0, r1); ql[s].x = bf16x2_of(r0, r1);
        qh[s].y = bf16x2_hi(x1.x, x1.y, r0, r1); ql[s].y = bf16x2_of(r0, r1);
        qh[s].z = bf16x2_hi(x2.x, x2.y, r0, r1); ql[s].z = bf16x2_of(r0, r1);
        qh[s].w = bf16x2_hi(x3.x, x3.y, r0, r1); ql[s].w = bf16x2_of(r0, r1);
    }

    float oacc[8][4] = {};
    float m0 = -INFINITY, m1 = -INFINITY, l0 = 0.f, l1 = 0.f;

    for (int kt = 0; kt < SS/64; kt++) {
        __syncthreads();
        // ---- stage K(hi,lo) and V(hi) rows: [key][d] bf16, stride 72 ----
#pragma unroll
        for (int r = 0; r < 4; r++) {
            int i = tid + 256*r;          // 0..1023
            int row = i >> 4, f4 = i & 15;
            int kg = kt*64 + row;
            int soff = row*KVSTR + f4*4;
            {
                float4 kv = *(const float4*)(base + (size_t)kg*(3*DD) + DD + h*HD + f4*4);
                float r0_, r1_, r2_, r3_;
                uint2 hw, lw;
                hw.x = bf16x2_hi(kv.x, kv.y, r0_, r1_);
                hw.y = bf16x2_hi(kv.z, kv.w, r2_, r3_);
                lw.x = bf16x2_of(r0_, r1_);
                lw.y = bf16x2_of(r2_, r3_);
                *(uint2*)&KhS[soff] = hw;
                *(uint2*)&KlS[soff] = lw;
            }
            {
                float4 vv = *(const float4*)(base + (size_t)kg*(3*DD) + 2*DD + h*HD + f4*4);
                uint2 hw;
                hw.x = bf16x2_of(vv.x, vv.y);
                hw.y = bf16x2_of(vv.z, vv.w);
                *(uint2*)&VhS[soff] = hw;
            }
        }
        __syncthreads();

        // ---- S = Q @ K^T (3-pass split bf16) ----
        float sacc[8][4] = {};
#pragma unroll
        for (int s = 0; s < 4; s++) {
#pragma unroll
            for (int nt = 0; nt < 8; nt++) {
                uint2 kh, kl;
                uint32_t off = nt*(8*KVSTR*2) + s*32;
                LDSM2(kh.x, kh.y, aKh + off);
                LDSM2(kl.x, kl.y, aKl + off);
                MMA_BF16(sacc[nt], qh[s], kh);
                MMA_BF16(sacc[nt], qh[s], kl);
                MMA_BF16(sacc[nt], ql[s], kh);
            }
        }

        // ---- scale + bias + online softmax ----
        int ktbase = kt*64;
        float mx0 = -INFINITY, mx1 = -INFINITY;
#pragma unroll
        for (int nt = 0; nt < 8; nt++) {
            int keyb = ktbase + nt*8 + 2*tq;
#pragma unroll
            for (int jj = 0; jj < 2; jj++) {
                int key = keyb + jj;
                int d0 = qr0 - key; d0 = d0 < 0 ? -d0 : d0;
                int d1 = qr1 - key; d1 = d1 < 0 ? -d1 : d1;
                float v0 = fmaf(sacc[nt][jj],   0.125f, bt[d0]);
                float v1 = fmaf(sacc[nt][2+jj], 0.125f, bt[d1]);
                sacc[nt][jj] = v0;   mx0 = fmaxf(mx0, v0);
                sacc[nt][2+jj] = v1; mx1 = fmaxf(mx1, v1);
            }
        }
        mx0 = fmaxf(mx0, __shfl_xor_sync(0xffffffffu, mx0, 1));
        mx0 = fmaxf(mx0, __shfl_xor_sync(0xffffffffu, mx0, 2));
        mx1 = fmaxf(mx1, __shfl_xor_sync(0xffffffffu, mx1, 1));
        mx1 = fmaxf(mx1, __shfl_xor_sync(0xffffffffu, mx1, 2));
        float newm0 = fmaxf(m0, mx0), newm1 = fmaxf(m1, mx1);
        float corr0 = fexp(m0 - newm0), corr1 = fexp(m1 - newm1);
        float rs0 = 0.f, rs1 = 0.f;
#pragma unroll
        for (int nt = 0; nt < 8; nt++) {
#pragma unroll
            for (int jj = 0; jj < 2; jj++) {
                float p0 = fexp(sacc[nt][jj]   - newm0);
                float p1 = fexp(sacc[nt][2+jj] - newm1);
                sacc[nt][jj] = p0;   rs0 += p0;
                sacc[nt][2+jj] = p1; rs1 += p1;
            }
        }
        rs0 += __shfl_xor_sync(0xffffffffu, rs0, 1);
        rs0 += __shfl_xor_sync(0xffffffffu, rs0, 2);
        rs1 += __shfl_xor_sync(0xffffffffu, rs1, 1);
        rs1 += __shfl_xor_sync(0xffffffffu, rs1, 2);
        l0 = l0*corr0 + rs0; m0 = newm0;
        l1 = l1*corr1 + rs1; m1 = newm1;
#pragma unroll
        for (int nt = 0; nt < 8; nt++) {
            oacc[nt][0] *= corr0; oacc[nt][1] *= corr0;
            oacc[nt][2] *= corr1; oacc[nt][3] *= corr1;
        }

        // ---- O += P @ V (2-pass: P split, V hi only) ----
#pragma unroll
        for (int s2 = 0; s2 < 4; s2++) {
            uint4 pah, pal;
            float r0_, r1_;
            pah.x = bf16x2_hi(sacc[2*s2][0],   sacc[2*s2][1],   r0_, r1_);
            pal.x = bf16x2_of(r0_, r1_);
            pah.y = bf16x2_hi(sacc[2*s2][2],   sacc[2*s2][3],   r0_, r1_);
            pal.y = bf16x2_of(r0_, r1_);
            pah.z = bf16x2_hi(sacc[2*s2+1][0], sacc[2*s2+1][1], r0_, r1_);
            pal.z = bf16x2_of(r0_, r1_);
            pah.w = bf16x2_hi(sacc[2*s2+1][2], sacc[2*s2+1][3], r0_, r1_);
            pal.w = bf16x2_of(r0_, r1_);
#pragma unroll
            for (int nt = 0; nt < 8; nt++) {
                uint2 vh;
                LDSM2T(vh.x, vh.y, aVh + s2*(16*KVSTR*2) + nt*16);
                MMA_BF16(oacc[nt], pah, vh);
                MMA_BF16(oacc[nt], pal, vh);
            }
        }
    }

    // ---- write ctx ----
    float inv0 = 1.f / l0, inv1 = 1.f / l1;
    float* c0 = ctx + ((size_t)b*SS + qr0)*DD + h*HD;
    float* c1 = ctx + ((size_t)b*SS + qr1)*DD + h*HD;
#pragma unroll
    for (int nt = 0; nt < 8; nt++) {
        int d = nt*8 + 2*tq;
        float2 v0 = { oacc[nt][0]*inv0, oacc[nt][1]*inv0 };
        float2 v1 = { oacc[nt][2]*inv1, oacc[nt][3]*inv1 };
        *(float2*)(c0 + d) = v0;
        *(float2*)(c1 + d) = v1;
    }
}

// ---------------- launcher --------------------------------------------------
extern "C" void kernel_launch(void* const* d_in, const int* in_sizes, int n_in,
                              void* d_out, int out_size) {
    const float* x      = (const float*)d_in[0];
    const float* w_qkv  = (const float*)d_in[1];
    const float* b_qkv  = (const float*)d_in[2];
    const float* w_out  = (const float*)d_in[3];
    const float* b_out  = (const float*)d_in[4];
    const float* gamma  = (const float*)d_in[5];
    const float* lnb    = (const float*)d_in[6];
    const float* beta   = (const float*)d_in[7];
    float* out = (float*)d_out;

    float *xn, *qkv, *ctx, *btab, *wtq, *wto;
    cudaGetSymbolAddress((void**)&xn,   g_xn);
    cudaGetSymbolAddress((void**)&qkv,  g_qkv);
    cudaGetSymbolAddress((void**)&ctx,  g_ctx);
    cudaGetSymbolAddress((void**)&btab, g_btab);
    cudaGetSymbolAddress((void**)&wtq,  g_wtq);
    cudaGetSymbolAddress((void**)&wto,  g_wto);

    transpose_kernel<<<dim3(3*DD/32, DD/32), dim3(32,8)>>>(w_qkv, wtq, DD, 3*DD);
    transpose_kernel<<<dim3(DD/32,   DD/32), dim3(32,8)>>>(w_out, wto, DD, DD);
    ln_kernel<<<ROWS, 256>>>(x, gamma, lnb, xn);
    bias_kernel<<<(SS+255)/256, 256>>>(beta, btab);

    gemm_bf16x3<false><<<dim3(3*DD/128, ROWS/128), 256>>>(
        xn, wtq, b_qkv, nullptr, qkv, 3*DD);
    flash_mma<<<dim3(SS/128, NH, BB), 256>>>(qkv, btab, ctx);
    gemm_bf16x3<true><<<dim3(DD/128, ROWS/128), 256>>>(
        ctx, wto, b_out, x, out, DD);
}

// round 7
// speedup vs baseline: 2.8255x; 1.1450x over previous
#include <cuda_runtime.h>
#include <cuda_bf16.h>
#include <math.h>
#include <stdint.h>

#define BB 2
#define SS 2048
#define DD 1024
#define NH 16
#define HD 64
#define ROWS (BB*SS)          // 4096
#define GK DD                 // 1024

// ---------------- scratch (static device globals: no allocation) ------------
__device__ unsigned short g_ah[ROWS*DD];     // A hi (xn, then ctx)
__device__ unsigned short g_al[ROWS*DD];     // A lo
__device__ unsigned short g_wqh[3*DD*DD];    // w_qkv^T hi  [N][K]
__device__ unsigned short g_wql[3*DD*DD];    // w_qkv^T lo
__device__ unsigned short g_woh[DD*DD];      // w_out^T hi
__device__ unsigned short g_wol[DD*DD];      // w_out^T lo
__device__ float g_qkv[ROWS*3*DD];           // 48 MB
__device__ float g_btab[SS];                 // 8 KB

// =================== helpers ================================================
__device__ __forceinline__ uint32_t bf16x2_of(float x0, float x1) {
    uint32_t r;
    asm("cvt.rn.bf16x2.f32 %0, %1, %2;" : "=r"(r) : "f"(x1), "f"(x0));
    return r;   // lo half = x0, hi half = x1
}
__device__ __forceinline__ uint32_t bf16x2_hi(float x0, float x1,
                                              float& r0, float& r1) {
    uint32_t h = bf16x2_of(x0, x1);
    float h0 = __int_as_float(h << 16);            // bf16 -> f32 exact
    float h1 = __int_as_float(h & 0xFFFF0000u);
    r0 = x0 - h0;
    r1 = x1 - h1;
    return h;
}

#define MMA_BF16(d, a, b) \
    asm volatile("mma.sync.aligned.m16n8k16.row.col.f32.bf16.bf16.f32 " \
        "{%0,%1,%2,%3}, {%4,%5,%6,%7}, {%8,%9}, {%0,%1,%2,%3};" \
        : "+f"((d)[0]), "+f"((d)[1]), "+f"((d)[2]), "+f"((d)[3]) \
        : "r"((a).x), "r"((a).y), "r"((a).z), "r"((a).w), \
          "r"((b).x), "r"((b).y))

#define LDSM2(r0, r1, a) \
    asm volatile("ldmatrix.sync.aligned.m8n8.x2.shared.b16 {%0,%1}, [%2];" \
        : "=r"(r0), "=r"(r1) : "r"(a))
#define LDSM2T(r0, r1, a) \
    asm volatile("ldmatrix.sync.aligned.m8n8.x2.trans.shared.b16 {%0,%1}, [%2];" \
        : "=r"(r0), "=r"(r1) : "r"(a))
#define LDSM4(r, a) \
    asm volatile("ldmatrix.sync.aligned.m8n8.x4.shared.b16 {%0,%1,%2,%3}, [%4];" \
        : "=r"((r).x), "=r"((r).y), "=r"((r).z), "=r"((r).w) : "r"(a))

// scalar fast exp (clamped; used for corr where arg may be -inf)
__device__ __forceinline__ float fexp(float x) {
    x = fmaxf(x, -80.f);
    float t = fmaf(x, 1.4426950408889634f, 12582912.0f);
    int n = __float_as_int(t) - 0x4B400000;
    float tm = t - 12582912.0f;
    float f = fmaf(x, 1.4426950408889634f, -tm);
    float p = 0.0096181291f;
    p = fmaf(p, f, 0.0555041087f);
    p = fmaf(p, f, 0.2402265070f);
    p = fmaf(p, f, 0.6931471806f);
    p = fmaf(p, f, 1.0f);
    return __int_as_float(__float_as_int(p) + (n << 23));
}

// packed f32x2 helpers
__device__ __forceinline__ uint64_t pk2(float a) {
    uint64_t r; asm("mov.b64 %0, {%1,%1};" : "=l"(r) : "f"(a)); return r;
}
__device__ __forceinline__ uint64_t f2fma(uint64_t a, uint64_t b, uint64_t c) {
    uint64_t d;
    asm("fma.rn.f32x2 %0, %1, %2, %3;" : "=l"(d) : "l"(a), "l"(b), "l"(c));
    return d;
}
__device__ __forceinline__ uint64_t f2add(uint64_t a, uint64_t b) {
    uint64_t d;
    asm("add.rn.f32x2 %0, %1, %2;" : "=l"(d) : "l"(a), "l"(b));
    return d;
}
__device__ __forceinline__ uint64_t f2mul(uint64_t a, uint64_t b) {
    uint64_t d;
    asm("mul.rn.f32x2 %0, %1, %2;" : "=l"(d) : "l"(a), "l"(b));
    return d;
}
// packed exp for two args in [-80, 0] (NOT -inf safe; degree-4 2^f)
struct ExpC { uint64_t cK, cM, cNM, cN1, c4, c3, c2, c1, c0; };
__device__ __forceinline__ void fexp_pair(float x0, float x1,
                                          float& y0, float& y1, const ExpC& C) {
    uint64_t xp; asm("mov.b64 %0, {%1,%2};" : "=l"(xp) : "f"(x0), "f"(x1));
    uint64_t t = f2fma(xp, C.cK, C.cM);
    uint32_t t0, t1;
    asm("mov.b64 {%0,%1}, %2;" : "=r"(t0), "=r"(t1) : "l"(t));
    uint64_t r = f2add(t, C.cNM);
    uint64_t f = f2fma(xp, C.cK, f2mul(r, C.cN1));
    uint64_t p = f2fma(C.c4, f, C.c3);
    p = f2fma(p, f, C.c2);
    p = f2fma(p, f, C.c1);
    p = f2fma(p, f, C.c0);
    uint32_t p0, p1;
    asm("mov.b64 {%0,%1}, %2;" : "=r"(p0), "=r"(p1) : "l"(p));
    y0 = __int_as_float((int)(p0 + ((t0 - 0x4B400000u) << 23)));
    y1 = __int_as_float((int)(p1 + ((t1 - 0x4B400000u) << 23)));
}

// ---------------- LayerNorm -> split bf16 hi/lo ------------------------------
__global__ void ln_kernel(const float* __restrict__ x,
                          const float* __restrict__ gamma,
                          const float* __restrict__ lnb,
                          unsigned short* __restrict__ ah,
                          unsigned short* __restrict__ al) {
    int row = blockIdx.x;
    const float* xr = x + (size_t)row * DD;
    float v[4];
    float s = 0.f;
#pragma unroll
    for (int i = 0; i < 4; i++) { v[i] = xr[threadIdx.x + 256*i]; s += v[i]; }
    __shared__ float red[8];
#pragma unroll
    for (int o = 16; o > 0; o >>= 1) s += __shfl_xor_sync(0xffffffffu, s, o);
    if ((threadIdx.x & 31) == 0) red[threadIdx.x >> 5] = s;
    __syncthreads();
    float tot = 0.f;
#pragma unroll
    for (int i = 0; i < 8; i++) tot += red[i];
    float mean = tot * (1.f/DD);
    float vs = 0.f;
#pragma unroll
    for (int i = 0; i < 4; i++) { float d = v[i]-mean; vs += d*d; }
    __syncthreads();
#pragma unroll
    for (int o = 16; o > 0; o >>= 1) vs += __shfl_xor_sync(0xffffffffu, vs, o);
    if ((threadIdx.x & 31) == 0) red[threadIdx.x >> 5] = vs;
    __syncthreads();
    float vtot = 0.f;
#pragma unroll
    for (int i = 0; i < 8; i++) vtot += red[i];
    float rstd = rsqrtf(vtot*(1.f/DD) + 1e-5f);
#pragma unroll
    for (int i = 0; i < 4; i++) {
        int c = threadIdx.x + 256*i;
        float y = (v[i]-mean)*rstd*gamma[c] + lnb[c];
        __nv_bfloat16 hb = __float2bfloat16_rn(y);
        ah[(size_t)row*DD + c] = __bfloat16_as_ushort(hb);
        al[(size_t)row*DD + c] = __bfloat16_as_ushort(
            __float2bfloat16_rn(y - __bfloat162float(hb)));
    }
}

__global__ void bias_kernel(const float* __restrict__ beta, float* __restrict__ tab) {
    int i = blockIdx.x*256 + threadIdx.x;
    if (i < SS) tab[i] = beta[0] * log1pf((float)i);
}

// ---------------- weight transpose + split: in[K][N] -> hi/lo [N][K] --------
__global__ void transpose_split(const float* __restrict__ in,
                                unsigned short* __restrict__ outh,
                                unsigned short* __restrict__ outl,
                                int K, int N) {
    __shared__ float t[32][33];
    int n0 = blockIdx.x*32, k0 = blockIdx.y*32;
    int tx = threadIdx.x, ty = threadIdx.y;   // 32 x 8
#pragma unroll
    for (int i = 0; i < 32; i += 8)
        t[ty+i][tx] = in[(size_t)(k0+ty+i)*N + n0+tx];
    __syncthreads();
#pragma unroll
    for (int i = 0; i < 32; i += 8) {
        float y = t[tx][ty+i];
        __nv_bfloat16 hb = __float2bfloat16_rn(y);
        size_t o = (size_t)(n0+ty+i)*K + k0+tx;
        outh[o] = __bfloat16_as_ushort(hb);
        outl[o] = __bfloat16_as_ushort(
            __float2bfloat16_rn(y - __bfloat162float(hb)));
    }
}

// =================== pre-split bf16x3 GEMM (ldmatrix) =======================
// C[M,N] = (Ah+Al)[M,K] @ (Bh+Bl)[N,K]^T (+bias +resid), 3-pass.
// CTA 128x128, chunk k=32; 8 warps = 4(m) x 2(n), warp tile 32x64.
#define GSTR 40   // smem row stride in bf16 elems (80 B -> conflict-free ldmatrix)

template<bool RESID>
__global__ void __launch_bounds__(256)
gemm_pre(const unsigned short* __restrict__ Ah, const unsigned short* __restrict__ Al,
         const unsigned short* __restrict__ Bh, const unsigned short* __restrict__ Bl,
         const float* __restrict__ bias, const float* __restrict__ resid,
         float* __restrict__ C, int N) {
    __shared__ unsigned short sAh[128*GSTR];
    __shared__ unsigned short sAl[128*GSTR];
    __shared__ unsigned short sBh[128*GSTR];
    __shared__ unsigned short sBl[128*GSTR];

    int tid = threadIdx.x, lane = tid & 31, wid = tid >> 5;
    int bm = blockIdx.y * 128, bn = blockIdx.x * 128;
    int wm = wid >> 1, wn = wid & 1;

    const unsigned short* Agh = Ah + (size_t)bm * GK;
    const unsigned short* Agl = Al + (size_t)bm * GK;
    const unsigned short* Bgh = Bh + (size_t)bn * GK;
    const unsigned short* Bgl = Bl + (size_t)bn * GK;

    uint32_t AhB = (uint32_t)__cvta_generic_to_shared(sAh);
    uint32_t AlB = (uint32_t)__cvta_generic_to_shared(sAl);
    uint32_t BhB = (uint32_t)__cvta_generic_to_shared(sBh);
    uint32_t BlB = (uint32_t)__cvta_generic_to_shared(sBl);

    // A x4: lanes 0-15 rows (lane&15) @k0; lanes 16-31 same rows @k+8
    uint32_t aAoff = 2*((lane & 15)*GSTR + ((lane >> 4) ? 8 : 0));
    // B x4 (two n8 tiles): row = (lane>>4)*8 + (lane&7); k+8 if lane&8
    uint32_t aBoff = 2*(((lane >> 4)*8 + (lane & 7))*GSTR + ((lane & 8) ? 8 : 0));

    float acc[2][8][4] = {};

    for (int c = 0; c < GK/32; c++) {
        // ---- stage: pure vector copies ----
#pragma unroll
        for (int it = 0; it < 2; it++) {
            int i = tid + 256*it;             // 0..511
            int row = i >> 2, q = i & 3;
            size_t goff = (size_t)row*GK + c*32 + q*8;
            int soff = row*GSTR + q*8;
            *(uint4*)&sAh[soff] = *(const uint4*)(Agh + goff);
            *(uint4*)&sAl[soff] = *(const uint4*)(Agl + goff);
            *(uint4*)&sBh[soff] = *(const uint4*)(Bgh + goff);
            *(uint4*)&sBl[soff] = *(const uint4*)(Bgl + goff);
        }
        __syncthreads();
        // ---- compute ----
#pragma unroll
        for (int s = 0; s < 2; s++) {
            uint4 ah[2], al[2];
#pragma unroll
            for (int mi = 0; mi < 2; mi++) {
                uint32_t off = aAoff + 2*((wm*32 + mi*16)*GSTR + s*16);
                LDSM4(ah[mi], AhB + off);
                LDSM4(al[mi], AlB + off);
            }
#pragma unroll
            for (int np = 0; np < 4; np++) {
                uint4 bh4, bl4;
                uint32_t off = aBoff + 2*((wn*64 + np*16)*GSTR + s*16);
                LDSM4(bh4, BhB + off);
                LDSM4(bl4, BlB + off);
                uint2 b0h = {bh4.x, bh4.y}, b1h = {bh4.z, bh4.w};
                uint2 b0l = {bl4.x, bl4.y}, b1l = {bl4.z, bl4.w};
#pragma unroll
                for (int mi = 0; mi < 2; mi++) {
                    MMA_BF16(acc[mi][2*np],   ah[mi], b0h);
                    MMA_BF16(acc[mi][2*np],   ah[mi], b0l);
                    MMA_BF16(acc[mi][2*np],   al[mi], b0h);
                    MMA_BF16(acc[mi][2*np+1], ah[mi], b1h);
                    MMA_BF16(acc[mi][2*np+1], ah[mi], b1l);
                    MMA_BF16(acc[mi][2*np+1], al[mi], b1h);
                }
            }
        }
        __syncthreads();
    }

    // ---- epilogue ----
    int g = lane >> 2, tq = lane & 3;
#pragma unroll
    for (int mi = 0; mi < 2; mi++) {
#pragma unroll
        for (int half = 0; half < 2; half++) {
            int row = bm + (wm*2 + mi)*16 + g + half*8;
            float* crow = C + (size_t)row * N;
            const float* rrow = resid + (size_t)row * N;
#pragma unroll
            for (int ni = 0; ni < 8; ni++) {
                int col = bn + (wn*8 + ni)*8 + tq*2;
                float2 v;
                v.x = acc[mi][ni][half*2 + 0] + bias[col];
                v.y = acc[mi][ni][half*2 + 1] + bias[col + 1];
                if (RESID) {
                    v.x += rrow[col];
                    v.y += rrow[col + 1];
                }
                *(float2*)(crow + col) = v;
            }
        }
    }
}

// =================== mma flash attention (ldmatrix staging) =================
// grid (SS/128, NH, BB), 256 thr = 8 warps; warp w owns q rows [w*16, w*16+16).
// K-tile = 64 keys. K (hi+lo) and V (hi) staged as row-major bf16 [key][72].
// Output ctx written as split bf16 hi/lo (feeds out-proj GEMM directly).
#define KVSTR 72

__global__ void __launch_bounds__(256)
flash_mma(const float* __restrict__ qkv, const float* __restrict__ btab,
          unsigned short* __restrict__ oh, unsigned short* __restrict__ ol) {
    __shared__ unsigned short KhS[64*KVSTR];
    __shared__ unsigned short KlS[64*KVSTR];
    __shared__ unsigned short VhS[64*KVSTR];
    __shared__ float bt[SS];

    int tid = threadIdx.x, lane = tid & 31, w = tid >> 5;
    int g = lane >> 2, tq = lane & 3;
    int q0 = blockIdx.x * 128;
    int h = blockIdx.y, b = blockIdx.z;
    const float* base = qkv + (size_t)b * SS * (3*DD);

    ExpC EC;
    EC.cK  = pk2(1.4426950408889634f);
    EC.cM  = pk2(12582912.0f);
    EC.cNM = pk2(-12582912.0f);
    EC.cN1 = pk2(-1.0f);
    EC.c4  = pk2(0.0096181291f);
    EC.c3  = pk2(0.0555041087f);
    EC.c2  = pk2(0.2402265070f);
    EC.c1  = pk2(0.6931471806f);
    EC.c0  = pk2(1.0f);

#pragma unroll
    for (int i = 0; i < SS/256; i++) bt[tid + 256*i] = btab[tid + 256*i];

    uint32_t KhB = (uint32_t)__cvta_generic_to_shared(KhS);
    uint32_t KlB = (uint32_t)__cvta_generic_to_shared(KlS);
    uint32_t VhB = (uint32_t)__cvta_generic_to_shared(VhS);
    uint32_t aKh = KhB + 2*((lane & 7)*KVSTR + ((lane & 8) ? 8 : 0));
    uint32_t aKl = KlB + 2*((lane & 7)*KVSTR + ((lane & 8) ? 8 : 0));
    uint32_t aVh = VhB + 2*((lane & 15)*KVSTR);

    // ---- Q fragments (once) ----
    int qr0 = q0 + w*16 + g, qr1 = qr0 + 8;
    const float* qp0 = base + (size_t)qr0*(3*DD) + h*HD;
    const float* qp1 = base + (size_t)qr1*(3*DD) + h*HD;
    uint4 qh[4], ql[4];
#pragma unroll
    for (int s = 0; s < 4; s++) {
        int c0 = s*16 + 2*tq;
        float2 x0 = *(const float2*)(qp0 + c0);
        float2 x1 = *(const float2*)(qp1 + c0);
        float2 x2 = *(const float2*)(qp0 + c0 + 8);
        float2 x3 = *(const float2*)(qp1 + c0 + 8);
        float r0, r1;
        qh[s].x = bf16x2_hi(x0.x, x0.y, r0, r1); ql[s].x = bf16x2_of(r0, r1);
        qh[s].y = bf16x2_hi(x1.x, x1.y, r0, r1); ql[s].y = bf16x2_of(r0, r1);
        qh[s].z = bf16x2_hi(x2.x, x2.y, r0, r1); ql[s].z = bf16x2_of(r0, r1);
        qh[s].w = bf16x2_hi(x3.x, x3.y, r0, r1); ql[s].w = bf16x2_of(r0, r1);
    }

    float oacc[8][4] = {};
    float m0 = -INFINITY, m1 = -INFINITY, l0 = 0.f, l1 = 0.f;

    for (int kt = 0; kt < SS/64; kt++) {
        __syncthreads();
#pragma unroll
        for (int r = 0; r < 4; r++) {
            int i = tid + 256*r;
            int row = i >> 4, f4 = i & 15;
            int kg = kt*64 + row;
            int soff = row*KVSTR + f4*4;
            {
                float4 kv = *(const float4*)(base + (size_t)kg*(3*DD) + DD + h*HD + f4*4);
                float r0_, r1_, r2_, r3_;
                uint2 hw, lw;
                hw.x = bf16x2_hi(kv.x, kv.y, r0_, r1_);
                hw.y = bf16x2_hi(kv.z, kv.w, r2_, r3_);
                lw.x = bf16x2_of(r0_, r1_);
                lw.y = bf16x2_of(r2_, r3_);
                *(uint2*)&KhS[soff] = hw;
                *(uint2*)&KlS[soff] = lw;
            }
            {
                float4 vv = *(const float4*)(base + (size_t)kg*(3*DD) + 2*DD + h*HD + f4*4);
                uint2 hw;
                hw.x = bf16x2_of(vv.x, vv.y);
                hw.y = bf16x2_of(vv.z, vv.w);
                *(uint2*)&VhS[soff] = hw;
            }
        }
        __syncthreads();

        // ---- S = Q @ K^T (3-pass) ----
        float sacc[8][4] = {};
#pragma unroll
        for (int s = 0; s < 4; s++) {
#pragma unroll
            for (int nt = 0; nt < 8; nt++) {
                uint2 kh, kl;
                uint32_t off = nt*(8*KVSTR*2) + s*32;
                LDSM2(kh.x, kh.y, aKh + off);
                LDSM2(kl.x, kl.y, aKl + off);
                MMA_BF16(sacc[nt], qh[s], kh);
                MMA_BF16(sacc[nt], qh[s], kl);
                MMA_BF16(sacc[nt], ql[s], kh);
            }
        }

        // ---- scale + bias + online softmax ----
        int ktbase = kt*64;
        float mx0 = -INFINITY, mx1 = -INFINITY;
#pragma unroll
        for (int nt = 0; nt < 8; nt++) {
            int keyb = ktbase + nt*8 + 2*tq;
#pragma unroll
            for (int jj = 0; jj < 2; jj++) {
                int key = keyb + jj;
                int d0 = qr0 - key; d0 = d0 < 0 ? -d0 : d0;
                int d1 = qr1 - key; d1 = d1 < 0 ? -d1 : d1;
                float v0 = fmaf(sacc[nt][jj],   0.125f, bt[d0]);
                float v1 = fmaf(sacc[nt][2+jj], 0.125f, bt[d1]);
                sacc[nt][jj] = v0;   mx0 = fmaxf(mx0, v0);
                sacc[nt][2+jj] = v1; mx1 = fmaxf(mx1, v1);
            }
        }
        mx0 = fmaxf(mx0, __shfl_xor_sync(0xffffffffu, mx0, 1));
        mx0 = fmaxf(mx0, __shfl_xor_sync(0xffffffffu, mx0, 2));
        mx1 = fmaxf(mx1, __shfl_xor_sync(0xffffffffu, mx1, 1));
        mx1 = fmaxf(mx1, __shfl_xor_sync(0xffffffffu, mx1, 2));
        float newm0 = fmaxf(m0, mx0), newm1 = fmaxf(m1, mx1);
        float corr0 = fexp(m0 - newm0), corr1 = fexp(m1 - newm1);
        float rs0 = 0.f, rs1 = 0.f;
#pragma unroll
        for (int nt = 0; nt < 8; nt++) {
            float p0, p1, p2, p3;
            fexp_pair(sacc[nt][0] - newm0, sacc[nt][1] - newm0, p0, p1, EC);
            fexp_pair(sacc[nt][2] - newm1, sacc[nt][3] - newm1, p2, p3, EC);
            sacc[nt][0] = p0; sacc[nt][1] = p1; rs0 += p0 + p1;
            sacc[nt][2] = p2; sacc[nt][3] = p3; rs1 += p2 + p3;
        }
        rs0 += __shfl_xor_sync(0xffffffffu, rs0, 1);
        rs0 += __shfl_xor_sync(0xffffffffu, rs0, 2);
        rs1 += __shfl_xor_sync(0xffffffffu, rs1, 1);
        rs1 += __shfl_xor_sync(0xffffffffu, rs1, 2);
        l0 = l0*corr0 + rs0; m0 = newm0;
        l1 = l1*corr1 + rs1; m1 = newm1;
#pragma unroll
        for (int nt = 0; nt < 8; nt++) {
            oacc[nt][0] *= corr0; oacc[nt][1] *= corr0;
            oacc[nt][2] *= corr1; oacc[nt][3] *= corr1;
        }

        // ---- O += P @ V (2-pass: P split, V hi only) ----
#pragma unroll
        for (int s2 = 0; s2 < 4; s2++) {
            uint4 pah, pal;
            float r0_, r1_;
            pah.x = bf16x2_hi(sacc[2*s2][0],   sacc[2*s2][1],   r0_, r1_);
            pal.x = bf16x2_of(r0_, r1_);
            pah.y = bf16x2_hi(sacc[2*s2][2],   sacc[2*s2][3],   r0_, r1_);
            pal.y = bf16x2_of(r0_, r1_);
            pah.z = bf16x2_hi(sacc[2*s2+1][0], sacc[2*s2+1][1], r0_, r1_);
            pal.z = bf16x2_of(r0_, r1_);
            pah.w = bf16x2_hi(sacc[2*s2+1][2], sacc[2*s2+1][3], r0_, r1_);
            pal.w = bf16x2_of(r0_, r1_);
#pragma unroll
            for (int nt = 0; nt < 8; nt++) {
                uint2 vh;
                LDSM2T(vh.x, vh.y, aVh + s2*(16*KVSTR*2) + nt*16);
                MMA_BF16(oacc[nt], pah, vh);
                MMA_BF16(oacc[nt], pal, vh);
            }
        }
    }

    // ---- write ctx as split bf16 hi/lo ----
    float inv0 = 1.f / l0, inv1 = 1.f / l1;
    size_t r0off = ((size_t)b*SS + qr0)*DD + h*HD;
    size_t r1off = ((size_t)b*SS + qr1)*DD + h*HD;
#pragma unroll
    for (int nt = 0; nt < 8; nt++) {
        int d = nt*8 + 2*tq;
        float l0_, l1_;
        uint32_t hh = bf16x2_hi(oacc[nt][0]*inv0, oacc[nt][1]*inv0, l0_, l1_);
        *(uint32_t*)&oh[r0off + d] = hh;
        *(uint32_t*)&ol[r0off + d] = bf16x2_of(l0_, l1_);
        uint32_t hh1 = bf16x2_hi(oacc[nt][2]*inv1, oacc[nt][3]*inv1, l0_, l1_);
        *(uint32_t*)&oh[r1off + d] = hh1;
        *(uint32_t*)&ol[r1off + d] = bf16x2_of(l0_, l1_);
    }
}

// ---------------- launcher --------------------------------------------------
extern "C" void kernel_launch(void* const* d_in, const int* in_sizes, int n_in,
                              void* d_out, int out_size) {
    const float* x      = (const float*)d_in[0];
    const float* w_qkv  = (const float*)d_in[1];
    const float* b_qkv  = (const float*)d_in[2];
    const float* w_out  = (const float*)d_in[3];
    const float* b_out  = (const float*)d_in[4];
    const float* gamma  = (const float*)d_in[5];
    const float* lnb    = (const float*)d_in[6];
    const float* beta   = (const float*)d_in[7];
    float* out = (float*)d_out;

    unsigned short *ah, *al, *wqh, *wql, *woh, *wol;
    float *qkv, *btab;
    cudaGetSymbolAddress((void**)&ah,   g_ah);
    cudaGetSymbolAddress((void**)&al,   g_al);
    cudaGetSymbolAddress((void**)&wqh,  g_wqh);
    cudaGetSymbolAddress((void**)&wql,  g_wql);
    cudaGetSymbolAddress((void**)&woh,  g_woh);
    cudaGetSymbolAddress((void**)&wol,  g_wol);
    cudaGetSymbolAddress((void**)&qkv,  g_qkv);
    cudaGetSymbolAddress((void**)&btab, g_btab);

    transpose_split<<<dim3(3*DD/32, DD/32), dim3(32,8)>>>(w_qkv, wqh, wql, DD, 3*DD);
    transpose_split<<<dim3(DD/32,   DD/32), dim3(32,8)>>>(w_out, woh, wol, DD, DD);
    ln_kernel<<<ROWS, 256>>>(x, gamma, lnb, ah, al);
    bias_kernel<<<(SS+255)/256, 256>>>(beta, btab);

    gemm_pre<false><<<dim3(3*DD/128, ROWS/128), 256>>>(
        ah, al, wqh, wql, b_qkv, nullptr, qkv, 3*DD);
    flash_mma<<<dim3(SS/128, NH, BB), 256>>>(qkv, btab, ah, al);
    gemm_pre<true><<<dim3(DD/128, ROWS/128), 256>>>(
        ah, al, woh, wol, b_out, x, out, DD);
}